// round 14
// baseline (speedup 1.0000x reference)
#include <cuda_runtime.h>
#include <cuda_bf16.h>
#include <math.h>
#include <stdint.h>

#define NN 100000
#define EE 800000
#define MNN 1000
#define MEE 8000
#define DD 128
#define HH 8
#define LL 16
#define BTT 256
#define VPP 15
#define SEE 10
#define RSQD 0.08838834764831845f

// ---------------- device scratch ----------------
__device__ float g_feat[NN*DD];
__device__ float g_q[NN*DD];
__device__ float g_k[NN*DD];
__device__ __nv_bfloat16 g_vb[NN*DD];
__device__ float g_agg[NN*DD];
__device__ float g_mfeat[MNN*DD];
__device__ float g_mq[MNN*DD];
__device__ float g_mk[MNN*DD];
__device__ float g_mv[MNN*DD];
__device__ float g_magg[MNN*DD];
__device__ float g_mout[MNN*DD];
__device__ float g_mef[MEE*DD];
__device__ float g_p2mn[MNN*DD];
__device__ float g_p1mn[MNN*HH];
__device__ __nv_bfloat16 g_p2meb[MEE*DD];
__device__ __nv_bfloat16 g_p1meb[MEE*HH];
__device__ int g_deg[NN];
__device__ int g_rowptr[NN+1];
__device__ int g_cursor[NN];
__device__ int g_esrc[EE];
__device__ int g_emid[EE];
__device__ int g_mdeg[MNN];
__device__ int g_mrowptr[MNN+1];
__device__ int g_mcursor[MNN];
__device__ int g_mesrc[MEE];
__device__ int g_meid[MEE];
__device__ int g_bsum[256];
__device__ int g_mbsum[8];
__device__ float g_bwf[16*16384];

struct BaseP { float tw[HH]; float n1[HH]; float e1[HH]; float n2[DD]; float e2[DD]; };
__device__ BaseP g_base;

// ---------------- PTX helpers ----------------
static __device__ __forceinline__ float to_tf32(float x){
    float r; asm("cvt.rna.tf32.f32 %0, %1;" : "=f"(r) : "f"(x)); return r;
}
static __device__ __forceinline__ void mma_tf32(float* d, const uint32_t* a, const uint32_t* b){
    asm volatile("mma.sync.aligned.m16n8k8.row.col.f32.tf32.tf32.f32 "
        "{%0,%1,%2,%3}, {%4,%5,%6,%7}, {%8,%9}, {%0,%1,%2,%3};"
        : "+f"(d[0]),"+f"(d[1]),"+f"(d[2]),"+f"(d[3])
        : "r"(a[0]),"r"(a[1]),"r"(a[2]),"r"(a[3]), "r"(b[0]),"r"(b[1]));
}
static __device__ __forceinline__ float4 bf4_to_f4(uint2 r){
    __nv_bfloat162 x = *(__nv_bfloat162*)&r.x, y = *(__nv_bfloat162*)&r.y;
    return make_float4(__low2float(x), __high2float(x), __low2float(y), __high2float(y));
}

// ---------------- fused small kernels ----------------
__global__ void k_zero2(int* a, int na, int* b, int nb){
    int i = blockIdx.x*blockDim.x + threadIdx.x;
    if (i < na) a[i] = 0;
    else if (i < na + nb) b[i - na] = 0;
}
__global__ void k_gather2(const float* __restrict__ emb,
                          const int* __restrict__ vals, const int* __restrict__ mvals,
                          float* __restrict__ o1, float* __restrict__ o2){
    int i = blockIdx.x*blockDim.x + threadIdx.x;
    if (i >= (NN+MNN)*32) return;
    int r = i >> 5, c = i & 31;
    if (r < NN) ((float4*)o1)[i] = ((const float4*)(emb + (size_t)vals[r]*DD))[c];
    else {
        int rr = r - NN;
        ((float4*)(o2 + (size_t)rr*DD))[c] = ((const float4*)(emb + (size_t)mvals[rr]*DD))[c];
    }
}
__global__ void k_hist2(const int* __restrict__ dstv, const int* __restrict__ mdst,
                        int* deg, int* mdeg){
    int i = blockIdx.x*blockDim.x + threadIdx.x;
    if (i < EE) atomicAdd(&deg[dstv[i]], 1);
    else if (i < EE + MEE) atomicAdd(&mdeg[mdst[i - EE]], 1);
}
__global__ void k_scatter_all(const int* __restrict__ dstv, const int* __restrict__ srcv,
                              const int* __restrict__ meid,
                              const int* __restrict__ mdst, const int* __restrict__ msrc,
                              int* cursor, int* es, int* em,
                              int* mcursor, int* mes, int* mem){
    int i = blockIdx.x*blockDim.x + threadIdx.x;
    if (i < EE){
        int p = atomicAdd(&cursor[dstv[i]], 1);
        es[p] = srcv[i];
        em[p] = meid[i];
    } else if (i < EE + MEE){
        int j = i - EE;
        int p = atomicAdd(&mcursor[mdst[j]], 1);
        mes[p] = msrc[j];
        mem[p] = j;
    }
}
__global__ void k_scan_local(const int* __restrict__ deg, int n, int* rowptr, int* bsum){
    __shared__ int ws[16];
    int tid = threadIdx.x;
    int i = blockIdx.x*512 + tid;
    int v = (i < n) ? deg[i] : 0;
    int x = v;
    #pragma unroll
    for (int o = 1; o < 32; o <<= 1){
        int y = __shfl_up_sync(0xffffffffu, x, o);
        if ((tid & 31) >= o) x += y;
    }
    if ((tid & 31) == 31) ws[tid >> 5] = x;
    __syncthreads();
    if (tid < 16){
        int y = ws[tid];
        #pragma unroll
        for (int o = 1; o < 16; o <<= 1){
            int z = __shfl_up_sync(0x0000ffffu, y, o);
            if (tid >= o) y += z;
        }
        ws[tid] = y;
    }
    __syncthreads();
    int add = (tid >= 32) ? ws[(tid >> 5) - 1] : 0;
    int excl = x - v + add;
    if (i < n) rowptr[i] = excl;
    if (tid == 511) bsum[blockIdx.x] = excl + v;
}
__global__ void k_scan_bsum(int* bsum, int nb){
    __shared__ int ws[8];
    int tid = threadIdx.x;
    int v = (tid < nb) ? bsum[tid] : 0;
    int x = v;
    #pragma unroll
    for (int o = 1; o < 32; o <<= 1){
        int y = __shfl_up_sync(0xffffffffu, x, o);
        if ((tid & 31) >= o) x += y;
    }
    if ((tid & 31) == 31) ws[tid >> 5] = x;
    __syncthreads();
    if (tid < 8){
        int y = ws[tid];
        #pragma unroll
        for (int o = 1; o < 8; o <<= 1){
            int z = __shfl_up_sync(0x000000ffu, y, o);
            if (tid >= o) y += z;
        }
        ws[tid] = y;
    }
    __syncthreads();
    int add = (tid >= 32) ? ws[(tid >> 5) - 1] : 0;
    if (tid < nb) bsum[tid] = x - v + add;
}
__global__ void k_scan_add(const int* __restrict__ bsum, int n, int total,
                           int* rowptr, int* cursor){
    int i = blockIdx.x*blockDim.x + threadIdx.x;
    if (i < n){
        int v = rowptr[i] + bsum[i >> 9];
        rowptr[i] = v; cursor[i] = v;
    }
    if (i == 0) rowptr[n] = total;
}

// ---------------- fused weight prep: all 16 matrices in one launch ----------------
__global__ void k_prep_w_all(const float* __restrict__ W0, const float* __restrict__ W1,
                             const float* __restrict__ W2, const float* __restrict__ W3,
                             const float* __restrict__ W4, const float* __restrict__ W5,
                             const float* __restrict__ W6, const float* __restrict__ W7,
                             float* __restrict__ out){
    const float* warr[8] = {W0, W1, W2, W3, W4, W5, W6, W7};
    int slot = blockIdx.y;             // 0..15
    int b = slot >> 3, wsel = slot & 7;
    const float* W = warr[wsel] + (size_t)b*16384;
    int i = blockIdx.x*256 + threadIdx.x;
    int n = i >> 7, k = i & 127;
    out[(size_t)slot*16384 + i] = to_tf32(W[(size_t)k*DD + n]);
}

// ---------------- tf32 GEMM (unchanged from R10) ----------------
#define GSM 101376
#define SB_OFF 33792

template<int KIND>
__global__ __launch_bounds__(256, 2) void k_gemm(
        const float* __restrict__ A, int rows,
        const float* __restrict__ B0, const float* __restrict__ B1, const float* __restrict__ B2,
        float* __restrict__ O0, float* __restrict__ O1, float* __restrict__ O2,
        __nv_bfloat16* __restrict__ O2b,
        const int* __restrict__ mid, const float* __restrict__ p2mn,
        float* __restrict__ copy_out){
    extern __shared__ char sp[];
    float* sA = (float*)sp;
    float* sB = (float*)(sp + SB_OFF);
    const uint32_t* sAu = (const uint32_t*)sA;
    const uint32_t* sBu = (const uint32_t*)sB;
    int tid = threadIdx.x, wid = tid >> 5, lane = tid & 31;
    int row0 = blockIdx.x*64;
    int g = lane >> 2, t = lane & 3;
    int m0 = (wid >> 2)*32, n0 = (wid & 3)*32;

    for (int i = tid; i < 2048; i += 256){
        int r = i >> 5, c4 = i & 31;
        float4 v = make_float4(0,0,0,0);
        if (row0 + r < rows) v = *(const float4*)(A + (size_t)(row0+r)*DD + c4*4);
        v.x = to_tf32(v.x); v.y = to_tf32(v.y); v.z = to_tf32(v.z); v.w = to_tf32(v.w);
        *(float4*)(sA + r*132 + c4*4) = v;
    }

    const float* Bp[3] = {B0, B1, B2};
    float* Op[3] = {O0, O1, O2};
    const int NWT = (KIND == 0) ? 3 : 1;

    #pragma unroll
    for (int iw = 0; iw < NWT; iw++){
        __syncthreads();
        const float* Bsrc = Bp[iw];
        for (int i = tid; i < 4096; i += 256){
            int n = i >> 5, c4 = i & 31;
            *(float4*)(sB + n*132 + c4*4) = ((const float4*)Bsrc)[i];
        }
        __syncthreads();

        float acc[2][4][4];
        #pragma unroll
        for (int mt = 0; mt < 2; mt++)
            #pragma unroll
            for (int nt = 0; nt < 4; nt++)
                #pragma unroll
                for (int j = 0; j < 4; j++) acc[mt][nt][j] = 0.0f;

        #pragma unroll
        for (int ks = 0; ks < 16; ks++){
            int k0 = ks*8;
            uint32_t a[2][4], b[4][2];
            #pragma unroll
            for (int mt = 0; mt < 2; mt++){
                int base = (m0 + mt*16 + g)*132 + k0 + t;
                a[mt][0] = sAu[base];
                a[mt][1] = sAu[base + 8*132];
                a[mt][2] = sAu[base + 4];
                a[mt][3] = sAu[base + 8*132 + 4];
            }
            #pragma unroll
            for (int nt = 0; nt < 4; nt++){
                int nb = (n0 + nt*8 + g)*132 + k0 + t;
                b[nt][0] = sBu[nb];
                b[nt][1] = sBu[nb + 4];
            }
            #pragma unroll
            for (int mt = 0; mt < 2; mt++)
                #pragma unroll
                for (int nt = 0; nt < 4; nt++)
                    mma_tf32(acc[mt][nt], a[mt], b[nt]);
        }

        float* O = Op[iw];
        bool isq = (KIND == 0) && (iw == 0);
        bool isvb = (KIND == 0) && (iw == 2) && (O2b != nullptr);
        #pragma unroll
        for (int mt = 0; mt < 2; mt++){
            #pragma unroll
            for (int half = 0; half < 2; half++){
                int gr = row0 + m0 + mt*16 + g + half*8;
                if (gr >= rows) continue;
                const float* pmrow = nullptr;
                if (isq && p2mn) pmrow = p2mn + (size_t)mid[gr]*DD;
                #pragma unroll
                for (int nt = 0; nt < 4; nt++){
                    int cc = n0 + nt*8 + t*2;
                    float v0 = acc[mt][nt][half*2 + 0];
                    float v1 = acc[mt][nt][half*2 + 1];
                    size_t gi = (size_t)gr*DD + cc;
                    if (KIND == 0){
                        if (isq){
                            float b0 = g_base.n2[cc], b1 = g_base.n2[cc+1];
                            if (pmrow){ b0 += pmrow[cc]; b1 += pmrow[cc+1]; }
                            v0 *= b0; v1 *= b1;
                        }
                        if (isvb){
                            __nv_bfloat162 hv = __floats2bfloat162_rn(v0, v1);
                            *(uint32_t*)((char*)O2b + gi*2) = *(uint32_t*)&hv;
                        } else {
                            *(float2*)(O + gi) = make_float2(v0, v1);
                        }
                    } else {
                        v0 = fmaxf(v0, 0.0f); v1 = fmaxf(v1, 0.0f);
                        if (copy_out) *(float2*)(copy_out + gi) = make_float2(v0, v1);
                        float2 f = *(float2*)(O + gi);
                        f.x += v0; f.y += v1;
                        *(float2*)(O + gi) = f;
                    }
                }
            }
        }
    }
}

// ---------------- meta learner ----------------
__device__ __forceinline__ void warp_ml_weights(float4 xv, int lane,
        const float* __restrict__ u, float* s){
    #pragma unroll
    for (int l2 = 0; l2 < LL; l2++){
        float4 uv = *(const float4*)(u + l2*DD + lane*4);
        float p = xv.x*uv.x + xv.y*uv.y + xv.z*uv.z + xv.w*uv.w;
        p += __shfl_xor_sync(0xffffffffu, p, 1);
        p += __shfl_xor_sync(0xffffffffu, p, 2);
        p += __shfl_xor_sync(0xffffffffu, p, 4);
        p += __shfl_xor_sync(0xffffffffu, p, 8);
        p += __shfl_xor_sync(0xffffffffu, p, 16);
        s[l2] = p * RSQD;
    }
    float mx = s[0];
    #pragma unroll
    for (int i = 1; i < LL; i++) mx = fmaxf(mx, s[i]);
    float zz = 0.0f;
    #pragma unroll
    for (int i = 0; i < LL; i++){ s[i] = __expf(s[i]-mx); zz += s[i]; }
    float inv = 1.0f / zz;
    #pragma unroll
    for (int i = 0; i < LL; i++) s[i] *= inv;
}

__device__ __forceinline__ void warp_meta_learner(float4 xv, int lane,
        const float* __restrict__ u, const float* __restrict__ W2, const float* __restrict__ W1,
        float* p2_out, float* p1_out){
    float s[LL];
    warp_ml_weights(xv, lane, u, s);
    if (p2_out){
        float4 acc = make_float4(0,0,0,0);
        #pragma unroll
        for (int l2 = 0; l2 < LL; l2++){
            float4 wv = *(const float4*)(W2 + l2*DD + lane*4);
            acc.x += s[l2]*wv.x; acc.y += s[l2]*wv.y; acc.z += s[l2]*wv.z; acc.w += s[l2]*wv.w;
        }
        *(float4*)(p2_out + lane*4) = acc;
    }
    if (p1_out && lane < HH){
        float a = 0.0f;
        #pragma unroll
        for (int l2 = 0; l2 < LL; l2++) a += s[l2]*W1[l2*HH + lane];
        p1_out[lane] = a;
    }
}

// fused: rows [0,MNN) node (fp32 out from Xn), rows [MNN,MNN+MEE) edge (bf16 out from Xe)
__global__ void k_meta_learner_all(const float* __restrict__ Xn, const float* __restrict__ Xe,
                                   const float* __restrict__ u, const float* __restrict__ W2,
                                   const float* __restrict__ W1,
                                   float* __restrict__ p2n, float* __restrict__ p1n,
                                   __nv_bfloat16* __restrict__ p2e, __nv_bfloat16* __restrict__ p1e){
    int w = (blockIdx.x*blockDim.x + threadIdx.x) >> 5;
    int lane = threadIdx.x & 31;
    if (w < MNN){
        float4 xv = *(const float4*)(Xn + (size_t)w*DD + lane*4);
        warp_meta_learner(xv, lane, u, W2, W1, p2n + (size_t)w*DD, p1n + (size_t)w*HH);
    } else if (w < MNN + MEE){
        int we = w - MNN;
        float4 xv = *(const float4*)(Xe + (size_t)we*DD + lane*4);
        float s[LL];
        warp_ml_weights(xv, lane, u, s);
        float4 acc = make_float4(0,0,0,0);
        #pragma unroll
        for (int l2 = 0; l2 < LL; l2++){
            float4 wv = *(const float4*)(W2 + l2*DD + lane*4);
            acc.x += s[l2]*wv.x; acc.y += s[l2]*wv.y; acc.z += s[l2]*wv.z; acc.w += s[l2]*wv.w;
        }
        __nv_bfloat162 h0 = __floats2bfloat162_rn(acc.x, acc.y);
        __nv_bfloat162 h1 = __floats2bfloat162_rn(acc.z, acc.w);
        uint2 pk; pk.x = *(uint32_t*)&h0; pk.y = *(uint32_t*)&h1;
        *(uint2*)(p2e + (size_t)we*DD + lane*4) = pk;
        if (lane < HH){
            float a = 0.0f;
            #pragma unroll
            for (int l2 = 0; l2 < LL; l2++) a += s[l2]*W1[l2*HH + lane];
            p1e[(size_t)we*HH + lane] = __float2bfloat16(a);
        }
    }
}

__global__ void k_static(const float* __restrict__ emb, const int* __restrict__ svals,
                         const int* __restrict__ ssrc, const int* __restrict__ sdst,
                         const float* __restrict__ u, const float* __restrict__ W2,
                         const float* __restrict__ W1){
    __shared__ float sagg[VPP][DD];
    int lane = threadIdx.x;
    for (int r = 0; r < VPP; r++)
        for (int c = lane; c < DD; c += 32) sagg[r][c] = 0.0f;
    __syncwarp();
    for (int e = 0; e < SEE; e++){
        int rdst = sdst[e];
        const float* ev = emb + (size_t)svals[ssrc[e]]*DD;
        for (int c = lane; c < DD; c += 32) sagg[rdst][c] += ev[c];
    }
    __syncwarp();
    float4 x;
    x = *(float4*)&sagg[0][lane*4];  warp_meta_learner(x, lane, u, W2, W1, nullptr,   g_base.tw);
    x = *(float4*)&sagg[3][lane*4];  warp_meta_learner(x, lane, u, W2, W1, nullptr,   g_base.n1);
    x = *(float4*)&sagg[6][lane*4];  warp_meta_learner(x, lane, u, W2, W1, g_base.n2, nullptr);
    x = *(float4*)&sagg[9][lane*4];  warp_meta_learner(x, lane, u, W2, W1, nullptr,   g_base.e1);
    x = *(float4*)&sagg[12][lane*4]; warp_meta_learner(x, lane, u, W2, W1, g_base.e2, nullptr);
}

// ---------------- edge conv: warp/dst-node, 4-way interleaved online softmax ----------------
static __device__ __forceinline__ void om_merge(float& m, float& z, float4& a,
                                                float mB, float zB, float4 aB){
    if (mB == -INFINITY) return;
    if (m == -INFINITY){ m = mB; z = zB; a = aB; return; }
    float mn = fmaxf(m, mB);
    float cA = __expf(m - mn), cB = __expf(mB - mn);
    z = z*cA + zB*cB;
    a.x = a.x*cA + aB.x*cB; a.y = a.y*cA + aB.y*cB;
    a.z = a.z*cA + aB.z*cB; a.w = a.w*cA + aB.w*cB;
    m = mn;
}

template<bool META>
__global__ void k_edge_conv(const int* __restrict__ rowptr,
                            const int* __restrict__ es, const int* __restrict__ em,
                            const int* __restrict__ mid_arr,
                            const float* __restrict__ q, const float* __restrict__ kf,
                            const float* __restrict__ vf, const __nv_bfloat16* __restrict__ vb,
                            const __nv_bfloat16* __restrict__ p2me,
                            const __nv_bfloat16* __restrict__ p1me,
                            const float* __restrict__ p1mn,
                            float* __restrict__ agg, float* __restrict__ keout, int n){
    int node = blockIdx.x*(blockDim.x >> 5) + (threadIdx.x >> 5);
    if (node >= n) return;
    int lane = threadIdx.x & 31, h = lane >> 2;
    int i0 = rowptr[node], i1 = rowptr[node+1];
    if (i0 == i1){
        *(float4*)(agg + (size_t)node*DD + lane*4) = make_float4(0,0,0,0);
        return;
    }
    float4 qv = *(const float4*)(q + (size_t)node*DD + lane*4);
    float p1n = g_base.n1[h];
    if (!META) p1n += p1mn[(size_t)mid_arr[node]*HH + h];
    float4 be2 = *(float4*)&g_base.e2[lane*4];
    float be1 = g_base.e1[h];

    float m4[4] = {-INFINITY, -INFINITY, -INFINITY, -INFINITY};
    float z4[4] = {0.0f, 0.0f, 0.0f, 0.0f};
    float4 ac4[4];
    #pragma unroll
    for (int j = 0; j < 4; j++) ac4[j] = make_float4(0,0,0,0);

    int i = i0;
    for (; i + 3 < i1; i += 4){
        int ss[4], ev[4];
        #pragma unroll
        for (int j = 0; j < 4; j++){ ss[j] = es[i+j]; ev[j] = em[i+j]; }
        float4 kv[4], vv[4], p2[4];
        float e1a[4];
        #pragma unroll
        for (int j = 0; j < 4; j++){
            kv[j] = *(const float4*)(kf + (size_t)ss[j]*DD + lane*4);
            if (META) vv[j] = *(const float4*)(vf + (size_t)ss[j]*DD + lane*4);
            else      vv[j] = bf4_to_f4(*(const uint2*)(vb + (size_t)ss[j]*DD + lane*4));
            p2[j] = be2; e1a[j] = be1;
            if (!META){
                float4 a = bf4_to_f4(*(const uint2*)(p2me + (size_t)ev[j]*DD + lane*4));
                p2[j].x += a.x; p2[j].y += a.y; p2[j].z += a.z; p2[j].w += a.w;
                e1a[j] += __bfloat162float(p1me[(size_t)ev[j]*HH + h]);
            }
        }
        float d[4];
        #pragma unroll
        for (int j = 0; j < 4; j++){
            float4 ke;
            ke.x = kv[j].x*p2[j].x; ke.y = kv[j].y*p2[j].y;
            ke.z = kv[j].z*p2[j].z; ke.w = kv[j].w*p2[j].w;
            if (META) *(float4*)(keout + (size_t)ev[j]*DD + lane*4) = ke;
            d[j] = qv.x*ke.x + qv.y*ke.y + qv.z*ke.z + qv.w*ke.w;
        }
        #pragma unroll
        for (int j = 0; j < 4; j++) d[j] += __shfl_xor_sync(0xffffffffu, d[j], 1);
        #pragma unroll
        for (int j = 0; j < 4; j++) d[j] += __shfl_xor_sync(0xffffffffu, d[j], 2);
        #pragma unroll
        for (int j = 0; j < 4; j++){
            float sc = d[j]*0.25f + e1a[j] + p1n;
            float mn0 = fmaxf(m4[j], sc);
            float c = __expf(m4[j] - mn0), w = __expf(sc - mn0);
            ac4[j].x = ac4[j].x*c + vv[j].x*w; ac4[j].y = ac4[j].y*c + vv[j].y*w;
            ac4[j].z = ac4[j].z*c + vv[j].z*w; ac4[j].w = ac4[j].w*c + vv[j].w*w;
            z4[j] = z4[j]*c + w; m4[j] = mn0;
        }
    }
    for (; i < i1; i++){
        int s0 = es[i], e0 = em[i];
        float4 kv0 = *(const float4*)(kf + (size_t)s0*DD + lane*4);
        float4 vv0;
        if (META) vv0 = *(const float4*)(vf + (size_t)s0*DD + lane*4);
        else      vv0 = bf4_to_f4(*(const uint2*)(vb + (size_t)s0*DD + lane*4));
        float4 p20 = be2; float e10 = be1;
        if (!META){
            float4 a0 = bf4_to_f4(*(const uint2*)(p2me + (size_t)e0*DD + lane*4));
            p20.x += a0.x; p20.y += a0.y; p20.z += a0.z; p20.w += a0.w;
            e10 += __bfloat162float(p1me[(size_t)e0*HH + h]);
        }
        float4 ke0;
        ke0.x = kv0.x*p20.x; ke0.y = kv0.y*p20.y; ke0.z = kv0.z*p20.z; ke0.w = kv0.w*p20.w;
        if (META) *(float4*)(keout + (size_t)e0*DD + lane*4) = ke0;
        float d0 = qv.x*ke0.x + qv.y*ke0.y + qv.z*ke0.z + qv.w*ke0.w;
        d0 += __shfl_xor_sync(0xffffffffu, d0, 1);
        d0 += __shfl_xor_sync(0xffffffffu, d0, 2);
        float sc0 = d0*0.25f + e10 + p1n;
        float mn0 = fmaxf(m4[0], sc0);
        float c0 = __expf(m4[0] - mn0), w0 = __expf(sc0 - mn0);
        ac4[0].x = ac4[0].x*c0 + vv0.x*w0; ac4[0].y = ac4[0].y*c0 + vv0.y*w0;
        ac4[0].z = ac4[0].z*c0 + vv0.z*w0; ac4[0].w = ac4[0].w*c0 + vv0.w*w0;
        z4[0] = z4[0]*c0 + w0; m4[0] = mn0;
    }
    om_merge(m4[0], z4[0], ac4[0], m4[1], z4[1], ac4[1]);
    om_merge(m4[2], z4[2], ac4[2], m4[3], z4[3], ac4[3]);
    om_merge(m4[0], z4[0], ac4[0], m4[2], z4[2], ac4[2]);
    float inv = 1.0f / (z4[0] + 1e-9f);
    float4 o;
    o.x = ac4[0].x*inv; o.y = ac4[0].y*inv; o.z = ac4[0].z*inv; o.w = ac4[0].w*inv;
    *(float4*)(agg + (size_t)node*DD + lane*4) = o;
}

__global__ void k_readout(const float* __restrict__ feat, const int* __restrict__ tix,
                          const int* __restrict__ mid_arr, const float* __restrict__ p1mn,
                          float* __restrict__ out, int first){
    int t = blockIdx.x*(blockDim.x >> 5) + (threadIdx.x >> 5);
    if (t >= BTT) return;
    int lane = threadIdx.x & 31, h = lane >> 2;
    int ti = tix[t];
    float4 f = *(const float4*)(feat + (size_t)ti*DD + lane*4);
    float s4 = f.x + f.y + f.z + f.w;
    float tw = g_base.tw[h] + p1mn[(size_t)mid_arr[ti]*HH + h];
    float p = tw * s4;
    p += __shfl_xor_sync(0xffffffffu, p, 1);
    p += __shfl_xor_sync(0xffffffffu, p, 2);
    p += __shfl_xor_sync(0xffffffffu, p, 4);
    p += __shfl_xor_sync(0xffffffffu, p, 8);
    p += __shfl_xor_sync(0xffffffffu, p, 16);
    if (lane == 0){
        if (first) out[t] = 0.5f * p;
        else       out[t] += 0.5f * p;
    }
}

// ---------------- host ----------------
extern "C" void kernel_launch(void* const* d_in, const int* in_sizes, int n_in,
                              void* d_out, int out_size){
    (void)in_sizes; (void)n_in; (void)out_size;
    const float* emb  = (const float*)d_in[0];
    const float* u    = (const float*)d_in[1];
    const float* W2l  = (const float*)d_in[2];
    const float* W1l  = (const float*)d_in[3];
    const float* Wq_m = (const float*)d_in[4];
    const float* Wk_m = (const float*)d_in[5];
    const float* Wv_m = (const float*)d_in[6];
    const float* Wo_m = (const float*)d_in[7];
    const float* Wq   = (const float*)d_in[8];
    const float* Wk   = (const float*)d_in[9];
    const float* Wv   = (const float*)d_in[10];
    const float* Wo   = (const float*)d_in[11];
    const int* node_vals      = (const int*)d_in[12];
    const int* meta_node_vals = (const int*)d_in[13];
    const int* srcv = (const int*)d_in[14];
    const int* dstv = (const int*)d_in[15];
    const int* msrc = (const int*)d_in[16];
    const int* mdst = (const int*)d_in[17];
    const int* mnid = (const int*)d_in[18];
    const int* meid = (const int*)d_in[19];
    const int* tix  = (const int*)d_in[20];
    const int* svals= (const int*)d_in[21];
    const int* ssrc = (const int*)d_in[22];
    const int* sdst = (const int*)d_in[23];
    float* out = (float*)d_out;

    void* vp;
    cudaGetSymbolAddress(&vp, g_feat);   float* p_feat  = (float*)vp;
    cudaGetSymbolAddress(&vp, g_q);      float* p_q     = (float*)vp;
    cudaGetSymbolAddress(&vp, g_k);      float* p_k     = (float*)vp;
    cudaGetSymbolAddress(&vp, g_vb);     __nv_bfloat16* p_vb = (__nv_bfloat16*)vp;
    cudaGetSymbolAddress(&vp, g_agg);    float* p_agg   = (float*)vp;
    cudaGetSymbolAddress(&vp, g_mfeat);  float* p_mfeat = (float*)vp;
    cudaGetSymbolAddress(&vp, g_mq);     float* p_mq    = (float*)vp;
    cudaGetSymbolAddress(&vp, g_mk);     float* p_mk    = (float*)vp;
    cudaGetSymbolAddress(&vp, g_mv);     float* p_mv    = (float*)vp;
    cudaGetSymbolAddress(&vp, g_magg);   float* p_magg  = (float*)vp;
    cudaGetSymbolAddress(&vp, g_mout);   float* p_mout  = (float*)vp;
    cudaGetSymbolAddress(&vp, g_mef);    float* p_mef   = (float*)vp;
    cudaGetSymbolAddress(&vp, g_p2mn);   float* p_p2mn  = (float*)vp;
    cudaGetSymbolAddress(&vp, g_p1mn);   float* p_p1mn  = (float*)vp;
    cudaGetSymbolAddress(&vp, g_p2meb);  __nv_bfloat16* p_p2meb = (__nv_bfloat16*)vp;
    cudaGetSymbolAddress(&vp, g_p1meb);  __nv_bfloat16* p_p1meb = (__nv_bfloat16*)vp;
    cudaGetSymbolAddress(&vp, g_deg);     int* p_deg    = (int*)vp;
    cudaGetSymbolAddress(&vp, g_rowptr);  int* p_rowptr = (int*)vp;
    cudaGetSymbolAddress(&vp, g_cursor);  int* p_cursor = (int*)vp;
    cudaGetSymbolAddress(&vp, g_esrc);    int* p_esrc   = (int*)vp;
    cudaGetSymbolAddress(&vp, g_emid);    int* p_emid   = (int*)vp;
    cudaGetSymbolAddress(&vp, g_mdeg);    int* p_mdeg   = (int*)vp;
    cudaGetSymbolAddress(&vp, g_mrowptr); int* p_mrowptr= (int*)vp;
    cudaGetSymbolAddress(&vp, g_mcursor); int* p_mcursor= (int*)vp;
    cudaGetSymbolAddress(&vp, g_mesrc);   int* p_mesrc  = (int*)vp;
    cudaGetSymbolAddress(&vp, g_meid);    int* p_meid   = (int*)vp;
    cudaGetSymbolAddress(&vp, g_bsum);    int* p_bsum   = (int*)vp;
    cudaGetSymbolAddress(&vp, g_mbsum);   int* p_mbsum  = (int*)vp;
    cudaGetSymbolAddress(&vp, g_bwf);     float* p_bwf  = (float*)vp;

    cudaFuncSetAttribute(k_gemm<0>, cudaFuncAttributeMaxDynamicSharedMemorySize, GSM);
    cudaFuncSetAttribute(k_gemm<1>, cudaFuncAttributeMaxDynamicSharedMemorySize, GSM);

    // CSR (both graphs, fused where possible)
    k_zero2<<<(NN+MNN+255)/256, 256>>>(p_deg, NN, p_mdeg, MNN);
    k_hist2<<<(EE+MEE+255)/256, 256>>>(dstv, mdst, p_deg, p_mdeg);
    {
        int nb = (NN + 511)/512;
        k_scan_local<<<nb, 512>>>(p_deg, NN, p_rowptr, p_bsum);
        k_scan_bsum<<<1, 256>>>(p_bsum, nb);
        k_scan_add<<<(NN+255)/256, 256>>>(p_bsum, NN, EE, p_rowptr, p_cursor);
        int mb = (MNN + 511)/512;
        k_scan_local<<<mb, 512>>>(p_mdeg, MNN, p_mrowptr, p_mbsum);
        k_scan_bsum<<<1, 256>>>(p_mbsum, mb);
        k_scan_add<<<(MNN+255)/256, 256>>>(p_mbsum, MNN, MEE, p_mrowptr, p_mcursor);
    }
    k_scatter_all<<<(EE+MEE+255)/256, 256>>>(dstv, srcv, meid, mdst, msrc,
                                             p_cursor, p_esrc, p_emid,
                                             p_mcursor, p_mesrc, p_meid);

    // gather embeddings (fused)
    k_gather2<<<((NN+MNN)*32+255)/256, 256>>>(emb, node_vals, meta_node_vals, p_feat, p_mfeat);

    // base params
    k_static<<<1, 32>>>(emb, svals, ssrc, sdst, u, W2l, W1l);

    // weight prep (one launch for all 16)
    {
        dim3 gp(64, 16);
        k_prep_w_all<<<gp, 256>>>(Wq_m, Wk_m, Wv_m, Wo_m, Wq, Wk, Wv, Wo, p_bwf);
    }

    #define BW(b, wsel) (p_bwf + (size_t)((b)*8+(wsel))*16384)

    int tmain = (NN + 63)/64;
    int tmeta = (MNN + 63)/64;
    for (int b = 0; b < 2; b++){
        // meta conv (all fp32)
        k_gemm<0><<<tmeta, 256, GSM>>>(p_mfeat, MNN, BW(b,0), BW(b,1), BW(b,2),
                                       p_mq, p_mk, p_mv, nullptr, nullptr, nullptr, nullptr);
        k_edge_conv<true><<<(MNN+7)/8, 256>>>(p_mrowptr, p_mesrc, p_meid, nullptr,
                                              p_mq, p_mk, p_mv, nullptr, nullptr, nullptr,
                                              nullptr, p_magg, p_mef, MNN);
        k_gemm<1><<<tmeta, 256, GSM>>>(p_magg, MNN, BW(b,3), nullptr, nullptr,
                                       p_mfeat, nullptr, nullptr, nullptr,
                                       nullptr, nullptr, p_mout);

        // meta learners (fused node fp32 + edge bf16)
        k_meta_learner_all<<<((MNN+MEE)*32+255)/256, 256>>>(p_mout, p_mef, u, W2l, W1l,
                                                            p_p2mn, p_p1mn, p_p2meb, p_p1meb);

        // main conv (v in bf16)
        k_gemm<0><<<tmain, 256, GSM>>>(p_feat, NN, BW(b,4), BW(b,5), BW(b,6),
                                       p_q, p_k, nullptr, p_vb, mnid, p_p2mn, nullptr);
        k_edge_conv<false><<<(NN+7)/8, 256>>>(p_rowptr, p_esrc, p_emid, mnid,
                                              p_q, p_k, nullptr, p_vb, p_p2meb, p_p1meb,
                                              p_p1mn, p_agg, nullptr, NN);
        k_gemm<1><<<tmain, 256, GSM>>>(p_agg, NN, BW(b,7), nullptr, nullptr,
                                       p_feat, nullptr, nullptr, nullptr,
                                       nullptr, nullptr, nullptr);

        // readout
        k_readout<<<(BTT+7)/8, 256>>>(p_feat, tix, mnid, p_p1mn, out, b == 0 ? 1 : 0);
    }
    #undef BW
}

// round 16
// speedup vs baseline: 1.0944x; 1.0944x over previous
#include <cuda_runtime.h>
#include <cuda_bf16.h>
#include <math.h>
#include <stdint.h>

#define NN 100000
#define EE 800000
#define MNN 1000
#define MEE 8000
#define DD 128
#define HH 8
#define LL 16
#define BTT 256
#define VPP 15
#define SEE 10
#define RSQD 0.08838834764831845f

// ---------------- device scratch ----------------
__device__ float g_feat[NN*DD];
__device__ float g_q[NN*DD];
__device__ float g_k[NN*DD];
__device__ __nv_bfloat16 g_vb[NN*DD];
__device__ float g_agg[NN*DD];
__device__ float g_mfeat[MNN*DD];
__device__ float g_mq[MNN*DD];
__device__ float g_mk[MNN*DD];
__device__ float g_mv[MNN*DD];
__device__ float g_magg[MNN*DD];
__device__ float g_mout[MNN*DD];
__device__ float g_mef[MEE*DD];
__device__ float g_p2mn[MNN*DD];
__device__ float g_p1mn[MNN*HH];
__device__ __nv_bfloat16 g_p2meb[MEE*DD];
__device__ __nv_bfloat16 g_p1meb[MEE*HH];
__device__ int g_deg[NN];
__device__ int g_rowptr[NN+1];
__device__ int g_cursor[NN];
__device__ int g_esrc[EE];
__device__ int g_emid[EE];
__device__ int g_mdeg[MNN];
__device__ int g_mrowptr[MNN+1];
__device__ int g_mcursor[MNN];
__device__ int g_mesrc[MEE];
__device__ int g_meid[MEE];
__device__ int g_bsum[256];
__device__ int g_mbsum[8];
__device__ float g_bwf[16*16384];

struct BaseP { float tw[HH]; float n1[HH]; float e1[HH]; float n2[DD]; float e2[DD]; };
__device__ BaseP g_base;

// ---------------- PTX helpers ----------------
static __device__ __forceinline__ float to_tf32(float x){
    float r; asm("cvt.rna.tf32.f32 %0, %1;" : "=f"(r) : "f"(x)); return r;
}
static __device__ __forceinline__ void mma_tf32(float* d, const uint32_t* a, const uint32_t* b){
    asm volatile("mma.sync.aligned.m16n8k8.row.col.f32.tf32.tf32.f32 "
        "{%0,%1,%2,%3}, {%4,%5,%6,%7}, {%8,%9}, {%0,%1,%2,%3};"
        : "+f"(d[0]),"+f"(d[1]),"+f"(d[2]),"+f"(d[3])
        : "r"(a[0]),"r"(a[1]),"r"(a[2]),"r"(a[3]), "r"(b[0]),"r"(b[1]));
}
static __device__ __forceinline__ float4 bf4_to_f4(uint2 r){
    __nv_bfloat162 x = *(__nv_bfloat162*)&r.x, y = *(__nv_bfloat162*)&r.y;
    return make_float4(__low2float(x), __high2float(x), __low2float(y), __high2float(y));
}

// ---------------- fused small kernels ----------------
__global__ void k_zero2(int* a, int na, int* b, int nb){
    int i = blockIdx.x*blockDim.x + threadIdx.x;
    if (i < na) a[i] = 0;
    else if (i < na + nb) b[i - na] = 0;
}
__global__ void k_gather2(const float* __restrict__ emb,
                          const int* __restrict__ vals, const int* __restrict__ mvals,
                          float* __restrict__ o1, float* __restrict__ o2){
    int i = blockIdx.x*blockDim.x + threadIdx.x;
    if (i >= (NN+MNN)*32) return;
    int r = i >> 5, c = i & 31;
    if (r < NN) ((float4*)o1)[i] = ((const float4*)(emb + (size_t)vals[r]*DD))[c];
    else {
        int rr = r - NN;
        ((float4*)(o2 + (size_t)rr*DD))[c] = ((const float4*)(emb + (size_t)mvals[rr]*DD))[c];
    }
}
__global__ void k_hist2(const int* __restrict__ dstv, const int* __restrict__ mdst,
                        int* deg, int* mdeg){
    int i = blockIdx.x*blockDim.x + threadIdx.x;
    if (i < EE) atomicAdd(&deg[dstv[i]], 1);
    else if (i < EE + MEE) atomicAdd(&mdeg[mdst[i - EE]], 1);
}
__global__ void k_scatter_all(const int* __restrict__ dstv, const int* __restrict__ srcv,
                              const int* __restrict__ meid,
                              const int* __restrict__ mdst, const int* __restrict__ msrc,
                              int* cursor, int* es, int* em,
                              int* mcursor, int* mes, int* mem){
    int i = blockIdx.x*blockDim.x + threadIdx.x;
    if (i < EE){
        int p = atomicAdd(&cursor[dstv[i]], 1);
        es[p] = srcv[i];
        em[p] = meid[i];
    } else if (i < EE + MEE){
        int j = i - EE;
        int p = atomicAdd(&mcursor[mdst[j]], 1);
        mes[p] = msrc[j];
        mem[p] = j;
    }
}
__global__ void k_scan_local(const int* __restrict__ deg, int n, int* rowptr, int* bsum){
    __shared__ int ws[16];
    int tid = threadIdx.x;
    int i = blockIdx.x*512 + tid;
    int v = (i < n) ? deg[i] : 0;
    int x = v;
    #pragma unroll
    for (int o = 1; o < 32; o <<= 1){
        int y = __shfl_up_sync(0xffffffffu, x, o);
        if ((tid & 31) >= o) x += y;
    }
    if ((tid & 31) == 31) ws[tid >> 5] = x;
    __syncthreads();
    if (tid < 16){
        int y = ws[tid];
        #pragma unroll
        for (int o = 1; o < 16; o <<= 1){
            int z = __shfl_up_sync(0x0000ffffu, y, o);
            if (tid >= o) y += z;
        }
        ws[tid] = y;
    }
    __syncthreads();
    int add = (tid >= 32) ? ws[(tid >> 5) - 1] : 0;
    int excl = x - v + add;
    if (i < n) rowptr[i] = excl;
    if (tid == 511) bsum[blockIdx.x] = excl + v;
}
__global__ void k_scan_bsum(int* bsum, int nb){
    __shared__ int ws[8];
    int tid = threadIdx.x;
    int v = (tid < nb) ? bsum[tid] : 0;
    int x = v;
    #pragma unroll
    for (int o = 1; o < 32; o <<= 1){
        int y = __shfl_up_sync(0xffffffffu, x, o);
        if ((tid & 31) >= o) x += y;
    }
    if ((tid & 31) == 31) ws[tid >> 5] = x;
    __syncthreads();
    if (tid < 8){
        int y = ws[tid];
        #pragma unroll
        for (int o = 1; o < 8; o <<= 1){
            int z = __shfl_up_sync(0x000000ffu, y, o);
            if (tid >= o) y += z;
        }
        ws[tid] = y;
    }
    __syncthreads();
    int add = (tid >= 32) ? ws[(tid >> 5) - 1] : 0;
    if (tid < nb) bsum[tid] = x - v + add;
}
__global__ void k_scan_add(const int* __restrict__ bsum, int n, int total,
                           int* rowptr, int* cursor){
    int i = blockIdx.x*blockDim.x + threadIdx.x;
    if (i < n){
        int v = rowptr[i] + bsum[i >> 9];
        rowptr[i] = v; cursor[i] = v;
    }
    if (i == 0) rowptr[n] = total;
}

// ---------------- fused weight prep ----------------
__global__ void k_prep_w_all(const float* __restrict__ W0, const float* __restrict__ W1,
                             const float* __restrict__ W2, const float* __restrict__ W3,
                             const float* __restrict__ W4, const float* __restrict__ W5,
                             const float* __restrict__ W6, const float* __restrict__ W7,
                             float* __restrict__ out){
    const float* warr[8] = {W0, W1, W2, W3, W4, W5, W6, W7};
    int slot = blockIdx.y;
    int b = slot >> 3, wsel = slot & 7;
    const float* W = warr[wsel] + (size_t)b*16384;
    int i = blockIdx.x*256 + threadIdx.x;
    int n = i >> 7, k = i & 127;
    out[(size_t)slot*16384 + i] = to_tf32(W[(size_t)k*DD + n]);
}

// ---------------- tf32 GEMM ----------------
#define GSM 101376
#define SB_OFF 33792

template<int KIND>
__global__ __launch_bounds__(256, 2) void k_gemm(
        const float* __restrict__ A, int rows,
        const float* __restrict__ B0, const float* __restrict__ B1, const float* __restrict__ B2,
        float* __restrict__ O0, float* __restrict__ O1, float* __restrict__ O2,
        __nv_bfloat16* __restrict__ O2b,
        const int* __restrict__ mid, const float* __restrict__ p2mn,
        float* __restrict__ copy_out){
    extern __shared__ char sp[];
    float* sA = (float*)sp;
    float* sB = (float*)(sp + SB_OFF);
    const uint32_t* sAu = (const uint32_t*)sA;
    const uint32_t* sBu = (const uint32_t*)sB;
    int tid = threadIdx.x, wid = tid >> 5, lane = tid & 31;
    int row0 = blockIdx.x*64;
    int g = lane >> 2, t = lane & 3;
    int m0 = (wid >> 2)*32, n0 = (wid & 3)*32;

    for (int i = tid; i < 2048; i += 256){
        int r = i >> 5, c4 = i & 31;
        float4 v = make_float4(0,0,0,0);
        if (row0 + r < rows) v = *(const float4*)(A + (size_t)(row0+r)*DD + c4*4);
        v.x = to_tf32(v.x); v.y = to_tf32(v.y); v.z = to_tf32(v.z); v.w = to_tf32(v.w);
        *(float4*)(sA + r*132 + c4*4) = v;
    }

    const float* Bp[3] = {B0, B1, B2};
    float* Op[3] = {O0, O1, O2};
    const int NWT = (KIND == 0) ? 3 : 1;

    #pragma unroll
    for (int iw = 0; iw < NWT; iw++){
        __syncthreads();
        const float* Bsrc = Bp[iw];
        for (int i = tid; i < 4096; i += 256){
            int n = i >> 5, c4 = i & 31;
            *(float4*)(sB + n*132 + c4*4) = ((const float4*)Bsrc)[i];
        }
        __syncthreads();

        float acc[2][4][4];
        #pragma unroll
        for (int mt = 0; mt < 2; mt++)
            #pragma unroll
            for (int nt = 0; nt < 4; nt++)
                #pragma unroll
                for (int j = 0; j < 4; j++) acc[mt][nt][j] = 0.0f;

        #pragma unroll
        for (int ks = 0; ks < 16; ks++){
            int k0 = ks*8;
            uint32_t a[2][4], b[4][2];
            #pragma unroll
            for (int mt = 0; mt < 2; mt++){
                int base = (m0 + mt*16 + g)*132 + k0 + t;
                a[mt][0] = sAu[base];
                a[mt][1] = sAu[base + 8*132];
                a[mt][2] = sAu[base + 4];
                a[mt][3] = sAu[base + 8*132 + 4];
            }
            #pragma unroll
            for (int nt = 0; nt < 4; nt++){
                int nb = (n0 + nt*8 + g)*132 + k0 + t;
                b[nt][0] = sBu[nb];
                b[nt][1] = sBu[nb + 4];
            }
            #pragma unroll
            for (int mt = 0; mt < 2; mt++)
                #pragma unroll
                for (int nt = 0; nt < 4; nt++)
                    mma_tf32(acc[mt][nt], a[mt], b[nt]);
        }

        float* O = Op[iw];
        bool isq = (KIND == 0) && (iw == 0);
        bool isvb = (KIND == 0) && (iw == 2) && (O2b != nullptr);
        #pragma unroll
        for (int mt = 0; mt < 2; mt++){
            #pragma unroll
            for (int half = 0; half < 2; half++){
                int gr = row0 + m0 + mt*16 + g + half*8;
                if (gr >= rows) continue;
                const float* pmrow = nullptr;
                if (isq && p2mn) pmrow = p2mn + (size_t)mid[gr]*DD;
                #pragma unroll
                for (int nt = 0; nt < 4; nt++){
                    int cc = n0 + nt*8 + t*2;
                    float v0 = acc[mt][nt][half*2 + 0];
                    float v1 = acc[mt][nt][half*2 + 1];
                    size_t gi = (size_t)gr*DD + cc;
                    if (KIND == 0){
                        if (isq){
                            float b0 = g_base.n2[cc], b1 = g_base.n2[cc+1];
                            if (pmrow){ b0 += pmrow[cc]; b1 += pmrow[cc+1]; }
                            v0 *= b0; v1 *= b1;
                        }
                        if (isvb){
                            __nv_bfloat162 hv = __floats2bfloat162_rn(v0, v1);
                            *(uint32_t*)((char*)O2b + gi*2) = *(uint32_t*)&hv;
                        } else {
                            *(float2*)(O + gi) = make_float2(v0, v1);
                        }
                    } else {
                        v0 = fmaxf(v0, 0.0f); v1 = fmaxf(v1, 0.0f);
                        if (copy_out) *(float2*)(copy_out + gi) = make_float2(v0, v1);
                        float2 f = *(float2*)(O + gi);
                        f.x += v0; f.y += v1;
                        *(float2*)(O + gi) = f;
                    }
                }
            }
        }
    }
}

// ---------------- meta learner ----------------
__device__ __forceinline__ void warp_ml_weights(float4 xv, int lane,
        const float* __restrict__ u, float* s){
    #pragma unroll
    for (int l2 = 0; l2 < LL; l2++){
        float4 uv = *(const float4*)(u + l2*DD + lane*4);
        float p = xv.x*uv.x + xv.y*uv.y + xv.z*uv.z + xv.w*uv.w;
        p += __shfl_xor_sync(0xffffffffu, p, 1);
        p += __shfl_xor_sync(0xffffffffu, p, 2);
        p += __shfl_xor_sync(0xffffffffu, p, 4);
        p += __shfl_xor_sync(0xffffffffu, p, 8);
        p += __shfl_xor_sync(0xffffffffu, p, 16);
        s[l2] = p * RSQD;
    }
    float mx = s[0];
    #pragma unroll
    for (int i = 1; i < LL; i++) mx = fmaxf(mx, s[i]);
    float zz = 0.0f;
    #pragma unroll
    for (int i = 0; i < LL; i++){ s[i] = __expf(s[i]-mx); zz += s[i]; }
    float inv = 1.0f / zz;
    #pragma unroll
    for (int i = 0; i < LL; i++) s[i] *= inv;
}

__device__ __forceinline__ void warp_meta_learner(float4 xv, int lane,
        const float* __restrict__ u, const float* __restrict__ W2, const float* __restrict__ W1,
        float* p2_out, float* p1_out){
    float s[LL];
    warp_ml_weights(xv, lane, u, s);
    if (p2_out){
        float4 acc = make_float4(0,0,0,0);
        #pragma unroll
        for (int l2 = 0; l2 < LL; l2++){
            float4 wv = *(const float4*)(W2 + l2*DD + lane*4);
            acc.x += s[l2]*wv.x; acc.y += s[l2]*wv.y; acc.z += s[l2]*wv.z; acc.w += s[l2]*wv.w;
        }
        *(float4*)(p2_out + lane*4) = acc;
    }
    if (p1_out && lane < HH){
        float a = 0.0f;
        #pragma unroll
        for (int l2 = 0; l2 < LL; l2++) a += s[l2]*W1[l2*HH + lane];
        p1_out[lane] = a;
    }
}

// fused: rows [0,MNN) node (fp32), rows [MNN,MNN+MEE) edge (bf16)
__global__ void k_meta_learner_all(const float* __restrict__ Xn, const float* __restrict__ Xe,
                                   const float* __restrict__ u, const float* __restrict__ W2,
                                   const float* __restrict__ W1,
                                   float* __restrict__ p2n, float* __restrict__ p1n,
                                   __nv_bfloat16* __restrict__ p2e, __nv_bfloat16* __restrict__ p1e){
    int w = (blockIdx.x*blockDim.x + threadIdx.x) >> 5;
    int lane = threadIdx.x & 31;
    if (w < MNN){
        float4 xv = *(const float4*)(Xn + (size_t)w*DD + lane*4);
        warp_meta_learner(xv, lane, u, W2, W1, p2n + (size_t)w*DD, p1n + (size_t)w*HH);
    } else if (w < MNN + MEE){
        int we = w - MNN;
        float4 xv = *(const float4*)(Xe + (size_t)we*DD + lane*4);
        float s[LL];
        warp_ml_weights(xv, lane, u, s);
        float4 acc = make_float4(0,0,0,0);
        #pragma unroll
        for (int l2 = 0; l2 < LL; l2++){
            float4 wv = *(const float4*)(W2 + l2*DD + lane*4);
            acc.x += s[l2]*wv.x; acc.y += s[l2]*wv.y; acc.z += s[l2]*wv.z; acc.w += s[l2]*wv.w;
        }
        __nv_bfloat162 h0 = __floats2bfloat162_rn(acc.x, acc.y);
        __nv_bfloat162 h1 = __floats2bfloat162_rn(acc.z, acc.w);
        uint2 pk; pk.x = *(uint32_t*)&h0; pk.y = *(uint32_t*)&h1;
        *(uint2*)(p2e + (size_t)we*DD + lane*4) = pk;
        if (lane < HH){
            float a = 0.0f;
            #pragma unroll
            for (int l2 = 0; l2 < LL; l2++) a += s[l2]*W1[l2*HH + lane];
            p1e[(size_t)we*HH + lane] = __float2bfloat16(a);
        }
    }
}

__global__ void k_static(const float* __restrict__ emb, const int* __restrict__ svals,
                         const int* __restrict__ ssrc, const int* __restrict__ sdst,
                         const float* __restrict__ u, const float* __restrict__ W2,
                         const float* __restrict__ W1){
    __shared__ float sagg[VPP][DD];
    int lane = threadIdx.x;
    for (int r = 0; r < VPP; r++)
        for (int c = lane; c < DD; c += 32) sagg[r][c] = 0.0f;
    __syncwarp();
    for (int e = 0; e < SEE; e++){
        int rdst = sdst[e];
        const float* ev = emb + (size_t)svals[ssrc[e]]*DD;
        for (int c = lane; c < DD; c += 32) sagg[rdst][c] += ev[c];
    }
    __syncwarp();
    float4 x;
    x = *(float4*)&sagg[0][lane*4];  warp_meta_learner(x, lane, u, W2, W1, nullptr,   g_base.tw);
    x = *(float4*)&sagg[3][lane*4];  warp_meta_learner(x, lane, u, W2, W1, nullptr,   g_base.n1);
    x = *(float4*)&sagg[6][lane*4];  warp_meta_learner(x, lane, u, W2, W1, g_base.n2, nullptr);
    x = *(float4*)&sagg[9][lane*4];  warp_meta_learner(x, lane, u, W2, W1, nullptr,   g_base.e1);
    x = *(float4*)&sagg[12][lane*4]; warp_meta_learner(x, lane, u, W2, W1, g_base.e2, nullptr);
}

// ---------------- edge conv: warp/dst-node, 2-way interleaved online softmax (R10 proven) ----------------
template<bool META>
__global__ void k_edge_conv(const int* __restrict__ rowptr,
                            const int* __restrict__ es, const int* __restrict__ em,
                            const int* __restrict__ mid_arr,
                            const float* __restrict__ q, const float* __restrict__ kf,
                            const float* __restrict__ vf, const __nv_bfloat16* __restrict__ vb,
                            const __nv_bfloat16* __restrict__ p2me,
                            const __nv_bfloat16* __restrict__ p1me,
                            const float* __restrict__ p1mn,
                            float* __restrict__ agg, float* __restrict__ keout, int n){
    int node = blockIdx.x*(blockDim.x >> 5) + (threadIdx.x >> 5);
    if (node >= n) return;
    int lane = threadIdx.x & 31, h = lane >> 2;
    int i0 = rowptr[node], i1 = rowptr[node+1];
    if (i0 == i1){
        *(float4*)(agg + (size_t)node*DD + lane*4) = make_float4(0,0,0,0);
        return;
    }
    float4 qv = *(const float4*)(q + (size_t)node*DD + lane*4);
    float p1n = g_base.n1[h];
    if (!META) p1n += p1mn[(size_t)mid_arr[node]*HH + h];
    float4 be2 = *(float4*)&g_base.e2[lane*4];
    float be1 = g_base.e1[h];

    float mA = -INFINITY, zA = 0.0f, mB = -INFINITY, zB = 0.0f;
    float4 accA = make_float4(0,0,0,0), accB = make_float4(0,0,0,0);

    int i = i0;
    for (; i + 1 < i1; i += 2){
        int s0 = es[i],  s1 = es[i+1];
        int e0 = em[i],  e1v = em[i+1];
        float4 kv0 = *(const float4*)(kf + (size_t)s0*DD + lane*4);
        float4 kv1 = *(const float4*)(kf + (size_t)s1*DD + lane*4);
        float4 vv0, vv1;
        if (META){
            vv0 = *(const float4*)(vf + (size_t)s0*DD + lane*4);
            vv1 = *(const float4*)(vf + (size_t)s1*DD + lane*4);
        } else {
            vv0 = bf4_to_f4(*(const uint2*)(vb + (size_t)s0*DD + lane*4));
            vv1 = bf4_to_f4(*(const uint2*)(vb + (size_t)s1*DD + lane*4));
        }
        float4 p20 = be2, p21 = be2;
        float e10 = be1, e11 = be1;
        if (!META){
            float4 a0 = bf4_to_f4(*(const uint2*)(p2me + (size_t)e0*DD  + lane*4));
            float4 a1 = bf4_to_f4(*(const uint2*)(p2me + (size_t)e1v*DD + lane*4));
            p20.x += a0.x; p20.y += a0.y; p20.z += a0.z; p20.w += a0.w;
            p21.x += a1.x; p21.y += a1.y; p21.z += a1.z; p21.w += a1.w;
            e10 += __bfloat162float(p1me[(size_t)e0*HH + h]);
            e11 += __bfloat162float(p1me[(size_t)e1v*HH + h]);
        }
        float4 ke0, ke1;
        ke0.x = kv0.x*p20.x; ke0.y = kv0.y*p20.y; ke0.z = kv0.z*p20.z; ke0.w = kv0.w*p20.w;
        ke1.x = kv1.x*p21.x; ke1.y = kv1.y*p21.y; ke1.z = kv1.z*p21.z; ke1.w = kv1.w*p21.w;
        if (META){
            *(float4*)(keout + (size_t)e0*DD  + lane*4) = ke0;
            *(float4*)(keout + (size_t)e1v*DD + lane*4) = ke1;
        }
        float d0 = qv.x*ke0.x + qv.y*ke0.y + qv.z*ke0.z + qv.w*ke0.w;
        float d1 = qv.x*ke1.x + qv.y*ke1.y + qv.z*ke1.z + qv.w*ke1.w;
        d0 += __shfl_xor_sync(0xffffffffu, d0, 1);
        d1 += __shfl_xor_sync(0xffffffffu, d1, 1);
        d0 += __shfl_xor_sync(0xffffffffu, d0, 2);
        d1 += __shfl_xor_sync(0xffffffffu, d1, 2);
        float sc0 = d0*0.25f + e10 + p1n;
        float sc1 = d1*0.25f + e11 + p1n;
        float mn0 = fmaxf(mA, sc0), mn1 = fmaxf(mB, sc1);
        float c0 = __expf(mA - mn0), w0 = __expf(sc0 - mn0);
        float c1 = __expf(mB - mn1), w1 = __expf(sc1 - mn1);
        accA.x = accA.x*c0 + vv0.x*w0; accA.y = accA.y*c0 + vv0.y*w0;
        accA.z = accA.z*c0 + vv0.z*w0; accA.w = accA.w*c0 + vv0.w*w0;
        accB.x = accB.x*c1 + vv1.x*w1; accB.y = accB.y*c1 + vv1.y*w1;
        accB.z = accB.z*c1 + vv1.z*w1; accB.w = accB.w*c1 + vv1.w*w1;
        zA = zA*c0 + w0; mA = mn0;
        zB = zB*c1 + w1; mB = mn1;
    }
    if (i < i1){
        int s0 = es[i], e0 = em[i];
        float4 kv0 = *(const float4*)(kf + (size_t)s0*DD + lane*4);
        float4 vv0;
        if (META) vv0 = *(const float4*)(vf + (size_t)s0*DD + lane*4);
        else      vv0 = bf4_to_f4(*(const uint2*)(vb + (size_t)s0*DD + lane*4));
        float4 p20 = be2; float e10 = be1;
        if (!META){
            float4 a0 = bf4_to_f4(*(const uint2*)(p2me + (size_t)e0*DD + lane*4));
            p20.x += a0.x; p20.y += a0.y; p20.z += a0.z; p20.w += a0.w;
            e10 += __bfloat162float(p1me[(size_t)e0*HH + h]);
        }
        float4 ke0;
        ke0.x = kv0.x*p20.x; ke0.y = kv0.y*p20.y; ke0.z = kv0.z*p20.z; ke0.w = kv0.w*p20.w;
        if (META) *(float4*)(keout + (size_t)e0*DD + lane*4) = ke0;
        float d0 = qv.x*ke0.x + qv.y*ke0.y + qv.z*ke0.z + qv.w*ke0.w;
        d0 += __shfl_xor_sync(0xffffffffu, d0, 1);
        d0 += __shfl_xor_sync(0xffffffffu, d0, 2);
        float sc0 = d0*0.25f + e10 + p1n;
        float mn0 = fmaxf(mA, sc0);
        float c0 = __expf(mA - mn0), w0 = __expf(sc0 - mn0);
        accA.x = accA.x*c0 + vv0.x*w0; accA.y = accA.y*c0 + vv0.y*w0;
        accA.z = accA.z*c0 + vv0.z*w0; accA.w = accA.w*c0 + vv0.w*w0;
        zA = zA*c0 + w0; mA = mn0;
    }
    float mn = fmaxf(mA, mB);
    float cA = __expf(mA - mn), cB = __expf(mB - mn);
    float z = zA*cA + zB*cB;
    float4 acc;
    acc.x = accA.x*cA + accB.x*cB; acc.y = accA.y*cA + accB.y*cB;
    acc.z = accA.z*cA + accB.z*cB; acc.w = accA.w*cA + accB.w*cB;
    float inv = 1.0f / (z + 1e-9f);
    float4 o;
    o.x = acc.x*inv; o.y = acc.y*inv; o.z = acc.z*inv; o.w = acc.w*inv;
    *(float4*)(agg + (size_t)node*DD + lane*4) = o;
}

__global__ void k_readout(const float* __restrict__ feat, const int* __restrict__ tix,
                          const int* __restrict__ mid_arr, const float* __restrict__ p1mn,
                          float* __restrict__ out, int first){
    int t = blockIdx.x*(blockDim.x >> 5) + (threadIdx.x >> 5);
    if (t >= BTT) return;
    int lane = threadIdx.x & 31, h = lane >> 2;
    int ti = tix[t];
    float4 f = *(const float4*)(feat + (size_t)ti*DD + lane*4);
    float s4 = f.x + f.y + f.z + f.w;
    float tw = g_base.tw[h] + p1mn[(size_t)mid_arr[ti]*HH + h];
    float p = tw * s4;
    p += __shfl_xor_sync(0xffffffffu, p, 1);
    p += __shfl_xor_sync(0xffffffffu, p, 2);
    p += __shfl_xor_sync(0xffffffffu, p, 4);
    p += __shfl_xor_sync(0xffffffffu, p, 8);
    p += __shfl_xor_sync(0xffffffffu, p, 16);
    if (lane == 0){
        if (first) out[t] = 0.5f * p;
        else       out[t] += 0.5f * p;
    }
}

// ---------------- host ----------------
extern "C" void kernel_launch(void* const* d_in, const int* in_sizes, int n_in,
                              void* d_out, int out_size){
    (void)in_sizes; (void)n_in; (void)out_size;
    const float* emb  = (const float*)d_in[0];
    const float* u    = (const float*)d_in[1];
    const float* W2l  = (const float*)d_in[2];
    const float* W1l  = (const float*)d_in[3];
    const float* Wq_m = (const float*)d_in[4];
    const float* Wk_m = (const float*)d_in[5];
    const float* Wv_m = (const float*)d_in[6];
    const float* Wo_m = (const float*)d_in[7];
    const float* Wq   = (const float*)d_in[8];
    const float* Wk   = (const float*)d_in[9];
    const float* Wv   = (const float*)d_in[10];
    const float* Wo   = (const float*)d_in[11];
    const int* node_vals      = (const int*)d_in[12];
    const int* meta_node_vals = (const int*)d_in[13];
    const int* srcv = (const int*)d_in[14];
    const int* dstv = (const int*)d_in[15];
    const int* msrc = (const int*)d_in[16];
    const int* mdst = (const int*)d_in[17];
    const int* mnid = (const int*)d_in[18];
    const int* meid = (const int*)d_in[19];
    const int* tix  = (const int*)d_in[20];
    const int* svals= (const int*)d_in[21];
    const int* ssrc = (const int*)d_in[22];
    const int* sdst = (const int*)d_in[23];
    float* out = (float*)d_out;

    void* vp;
    cudaGetSymbolAddress(&vp, g_feat);   float* p_feat  = (float*)vp;
    cudaGetSymbolAddress(&vp, g_q);      float* p_q     = (float*)vp;
    cudaGetSymbolAddress(&vp, g_k);      float* p_k     = (float*)vp;
    cudaGetSymbolAddress(&vp, g_vb);     __nv_bfloat16* p_vb = (__nv_bfloat16*)vp;
    cudaGetSymbolAddress(&vp, g_agg);    float* p_agg   = (float*)vp;
    cudaGetSymbolAddress(&vp, g_mfeat);  float* p_mfeat = (float*)vp;
    cudaGetSymbolAddress(&vp, g_mq);     float* p_mq    = (float*)vp;
    cudaGetSymbolAddress(&vp, g_mk);     float* p_mk    = (float*)vp;
    cudaGetSymbolAddress(&vp, g_mv);     float* p_mv    = (float*)vp;
    cudaGetSymbolAddress(&vp, g_magg);   float* p_magg  = (float*)vp;
    cudaGetSymbolAddress(&vp, g_mout);   float* p_mout  = (float*)vp;
    cudaGetSymbolAddress(&vp, g_mef);    float* p_mef   = (float*)vp;
    cudaGetSymbolAddress(&vp, g_p2mn);   float* p_p2mn  = (float*)vp;
    cudaGetSymbolAddress(&vp, g_p1mn);   float* p_p1mn  = (float*)vp;
    cudaGetSymbolAddress(&vp, g_p2meb);  __nv_bfloat16* p_p2meb = (__nv_bfloat16*)vp;
    cudaGetSymbolAddress(&vp, g_p1meb);  __nv_bfloat16* p_p1meb = (__nv_bfloat16*)vp;
    cudaGetSymbolAddress(&vp, g_deg);     int* p_deg    = (int*)vp;
    cudaGetSymbolAddress(&vp, g_rowptr);  int* p_rowptr = (int*)vp;
    cudaGetSymbolAddress(&vp, g_cursor);  int* p_cursor = (int*)vp;
    cudaGetSymbolAddress(&vp, g_esrc);    int* p_esrc   = (int*)vp;
    cudaGetSymbolAddress(&vp, g_emid);    int* p_emid   = (int*)vp;
    cudaGetSymbolAddress(&vp, g_mdeg);    int* p_mdeg   = (int*)vp;
    cudaGetSymbolAddress(&vp, g_mrowptr); int* p_mrowptr= (int*)vp;
    cudaGetSymbolAddress(&vp, g_mcursor); int* p_mcursor= (int*)vp;
    cudaGetSymbolAddress(&vp, g_mesrc);   int* p_mesrc  = (int*)vp;
    cudaGetSymbolAddress(&vp, g_meid);    int* p_meid   = (int*)vp;
    cudaGetSymbolAddress(&vp, g_bsum);    int* p_bsum   = (int*)vp;
    cudaGetSymbolAddress(&vp, g_mbsum);   int* p_mbsum  = (int*)vp;
    cudaGetSymbolAddress(&vp, g_bwf);     float* p_bwf  = (float*)vp;

    cudaFuncSetAttribute(k_gemm<0>, cudaFuncAttributeMaxDynamicSharedMemorySize, GSM);
    cudaFuncSetAttribute(k_gemm<1>, cudaFuncAttributeMaxDynamicSharedMemorySize, GSM);

    // CSR (both graphs, fused)
    k_zero2<<<(NN+MNN+255)/256, 256>>>(p_deg, NN, p_mdeg, MNN);
    k_hist2<<<(EE+MEE+255)/256, 256>>>(dstv, mdst, p_deg, p_mdeg);
    {
        int nb = (NN + 511)/512;
        k_scan_local<<<nb, 512>>>(p_deg, NN, p_rowptr, p_bsum);
        k_scan_bsum<<<1, 256>>>(p_bsum, nb);
        k_scan_add<<<(NN+255)/256, 256>>>(p_bsum, NN, EE, p_rowptr, p_cursor);
        int mb = (MNN + 511)/512;
        k_scan_local<<<mb, 512>>>(p_mdeg, MNN, p_mrowptr, p_mbsum);
        k_scan_bsum<<<1, 256>>>(p_mbsum, mb);
        k_scan_add<<<(MNN+255)/256, 256>>>(p_mbsum, MNN, MEE, p_mrowptr, p_mcursor);
    }
    k_scatter_all<<<(EE+MEE+255)/256, 256>>>(dstv, srcv, meid, mdst, msrc,
                                             p_cursor, p_esrc, p_emid,
                                             p_mcursor, p_mesrc, p_meid);

    // gather embeddings (fused)
    k_gather2<<<((NN+MNN)*32+255)/256, 256>>>(emb, node_vals, meta_node_vals, p_feat, p_mfeat);

    // base params
    k_static<<<1, 32>>>(emb, svals, ssrc, sdst, u, W2l, W1l);

    // weight prep (one launch)
    {
        dim3 gp(64, 16);
        k_prep_w_all<<<gp, 256>>>(Wq_m, Wk_m, Wv_m, Wo_m, Wq, Wk, Wv, Wo, p_bwf);
    }

    #define BW(b, wsel) (p_bwf + (size_t)((b)*8+(wsel))*16384)

    int tmain = (NN + 63)/64;
    int tmeta = (MNN + 63)/64;
    for (int b = 0; b < 2; b++){
        // meta conv (all fp32)
        k_gemm<0><<<tmeta, 256, GSM>>>(p_mfeat, MNN, BW(b,0), BW(b,1), BW(b,2),
                                       p_mq, p_mk, p_mv, nullptr, nullptr, nullptr, nullptr);
        k_edge_conv<true><<<(MNN+7)/8, 256>>>(p_mrowptr, p_mesrc, p_meid, nullptr,
                                              p_mq, p_mk, p_mv, nullptr, nullptr, nullptr,
                                              nullptr, p_magg, p_mef, MNN);
        k_gemm<1><<<tmeta, 256, GSM>>>(p_magg, MNN, BW(b,3), nullptr, nullptr,
                                       p_mfeat, nullptr, nullptr, nullptr,
                                       nullptr, nullptr, p_mout);

        // meta learners (fused node fp32 + edge bf16)
        k_meta_learner_all<<<((MNN+MEE)*32+255)/256, 256>>>(p_mout, p_mef, u, W2l, W1l,
                                                            p_p2mn, p_p1mn, p_p2meb, p_p1meb);

        // main conv (v in bf16)
        k_gemm<0><<<tmain, 256, GSM>>>(p_feat, NN, BW(b,4), BW(b,5), BW(b,6),
                                       p_q, p_k, nullptr, p_vb, mnid, p_p2mn, nullptr);
        k_edge_conv<false><<<(NN+7)/8, 256>>>(p_rowptr, p_esrc, p_emid, mnid,
                                              p_q, p_k, nullptr, p_vb, p_p2meb, p_p1meb,
                                              p_p1mn, p_agg, nullptr, NN);
        k_gemm<1><<<tmain, 256, GSM>>>(p_agg, NN, BW(b,7), nullptr, nullptr,
                                       p_feat, nullptr, nullptr, nullptr,
                                       nullptr, nullptr, nullptr);

        // readout
        k_readout<<<(BTT+7)/8, 256>>>(p_feat, tix, mnid, p_p1mn, out, b == 0 ? 1 : 0);
    }
    #undef BW
}

// round 17
// speedup vs baseline: 1.1428x; 1.0442x over previous
#include <cuda_runtime.h>
#include <cuda_bf16.h>
#include <math.h>
#include <stdint.h>

#define NN 100000
#define EE 800000
#define MNN 1000
#define MEE 8000
#define DD 128
#define HH 8
#define LL 16
#define BTT 256
#define VPP 15
#define SEE 10
#define RSQD 0.08838834764831845f

// ---------------- device scratch ----------------
__device__ float g_feat[NN*DD];
__device__ float g_q[NN*DD];
__device__ float g_k[NN*DD];
__device__ __nv_bfloat16 g_vb[NN*DD];
__device__ float g_agg[NN*DD];
__device__ float g_mfeat[MNN*DD];
__device__ float g_mq[MNN*DD];
__device__ float g_mk[MNN*DD];
__device__ float g_mv[MNN*DD];
__device__ float g_magg[MNN*DD];
__device__ float g_mout[MNN*DD];
__device__ float g_mef[MEE*DD];
__device__ float g_p2mn[MNN*DD];
__device__ float g_p1mn[MNN*HH];
__device__ __nv_bfloat16 g_p2meb[MEE*DD];
__device__ __nv_bfloat16 g_p1meb[MEE*HH];
__device__ int g_deg[NN];
__device__ int g_rowptr[NN+1];
__device__ int g_cursor[NN];
__device__ int g_esrc[EE];
__device__ int g_emid[EE];
__device__ int g_mdeg[MNN];
__device__ int g_mrowptr[MNN+1];
__device__ int g_mcursor[MNN];
__device__ int g_mesrc[MEE];
__device__ int g_meid[MEE];
__device__ int g_bsum[256];
__device__ int g_mbsum[8];
__device__ float g_bwf[16*16384];

struct BaseP { float tw[HH]; float n1[HH]; float e1[HH]; float n2[DD]; float e2[DD]; };
__device__ BaseP g_base;

// ---------------- PTX helpers ----------------
static __device__ __forceinline__ float to_tf32(float x){
    float r; asm("cvt.rna.tf32.f32 %0, %1;" : "=f"(r) : "f"(x)); return r;
}
static __device__ __forceinline__ void mma_tf32(float* d, const uint32_t* a, const uint32_t* b){
    asm volatile("mma.sync.aligned.m16n8k8.row.col.f32.tf32.tf32.f32 "
        "{%0,%1,%2,%3}, {%4,%5,%6,%7}, {%8,%9}, {%0,%1,%2,%3};"
        : "+f"(d[0]),"+f"(d[1]),"+f"(d[2]),"+f"(d[3])
        : "r"(a[0]),"r"(a[1]),"r"(a[2]),"r"(a[3]), "r"(b[0]),"r"(b[1]));
}
static __device__ __forceinline__ float4 bf4_to_f4(uint2 r){
    __nv_bfloat162 x = *(__nv_bfloat162*)&r.x, y = *(__nv_bfloat162*)&r.y;
    return make_float4(__low2float(x), __high2float(x), __low2float(y), __high2float(y));
}

// ---------------- fused small kernels ----------------
__global__ void k_zero2(int* a, int na, int* b, int nb){
    int i = blockIdx.x*blockDim.x + threadIdx.x;
    if (i < na) a[i] = 0;
    else if (i < na + nb) b[i - na] = 0;
}
__global__ void k_gather2(const float* __restrict__ emb,
                          const int* __restrict__ vals, const int* __restrict__ mvals,
                          float* __restrict__ o1, float* __restrict__ o2){
    int i = blockIdx.x*blockDim.x + threadIdx.x;
    if (i >= (NN+MNN)*32) return;
    int r = i >> 5, c = i & 31;
    if (r < NN) ((float4*)o1)[i] = ((const float4*)(emb + (size_t)vals[r]*DD))[c];
    else {
        int rr = r - NN;
        ((float4*)(o2 + (size_t)rr*DD))[c] = ((const float4*)(emb + (size_t)mvals[rr]*DD))[c];
    }
}
__global__ void k_hist2(const int* __restrict__ dstv, const int* __restrict__ mdst,
                        int* deg, int* mdeg){
    int i = blockIdx.x*blockDim.x + threadIdx.x;
    if (i < EE) atomicAdd(&deg[dstv[i]], 1);
    else if (i < EE + MEE) atomicAdd(&mdeg[mdst[i - EE]], 1);
}
__global__ void k_scatter_all(const int* __restrict__ dstv, const int* __restrict__ srcv,
                              const int* __restrict__ meid,
                              const int* __restrict__ mdst, const int* __restrict__ msrc,
                              int* cursor, int* es, int* em,
                              int* mcursor, int* mes, int* mem){
    int i = blockIdx.x*blockDim.x + threadIdx.x;
    if (i < EE){
        int p = atomicAdd(&cursor[dstv[i]], 1);
        es[p] = srcv[i];
        em[p] = meid[i];
    } else if (i < EE + MEE){
        int j = i - EE;
        int p = atomicAdd(&mcursor[mdst[j]], 1);
        mes[p] = msrc[j];
        mem[p] = j;
    }
}
__global__ void k_scan_local(const int* __restrict__ deg, int n, int* rowptr, int* bsum){
    __shared__ int ws[16];
    int tid = threadIdx.x;
    int i = blockIdx.x*512 + tid;
    int v = (i < n) ? deg[i] : 0;
    int x = v;
    #pragma unroll
    for (int o = 1; o < 32; o <<= 1){
        int y = __shfl_up_sync(0xffffffffu, x, o);
        if ((tid & 31) >= o) x += y;
    }
    if ((tid & 31) == 31) ws[tid >> 5] = x;
    __syncthreads();
    if (tid < 16){
        int y = ws[tid];
        #pragma unroll
        for (int o = 1; o < 16; o <<= 1){
            int z = __shfl_up_sync(0x0000ffffu, y, o);
            if (tid >= o) y += z;
        }
        ws[tid] = y;
    }
    __syncthreads();
    int add = (tid >= 32) ? ws[(tid >> 5) - 1] : 0;
    int excl = x - v + add;
    if (i < n) rowptr[i] = excl;
    if (tid == 511) bsum[blockIdx.x] = excl + v;
}
__global__ void k_scan_bsum(int* bsum, int nb){
    __shared__ int ws[8];
    int tid = threadIdx.x;
    int v = (tid < nb) ? bsum[tid] : 0;
    int x = v;
    #pragma unroll
    for (int o = 1; o < 32; o <<= 1){
        int y = __shfl_up_sync(0xffffffffu, x, o);
        if ((tid & 31) >= o) x += y;
    }
    if ((tid & 31) == 31) ws[tid >> 5] = x;
    __syncthreads();
    if (tid < 8){
        int y = ws[tid];
        #pragma unroll
        for (int o = 1; o < 8; o <<= 1){
            int z = __shfl_up_sync(0x000000ffu, y, o);
            if (tid >= o) y += z;
        }
        ws[tid] = y;
    }
    __syncthreads();
    int add = (tid >= 32) ? ws[(tid >> 5) - 1] : 0;
    if (tid < nb) bsum[tid] = x - v + add;
}
__global__ void k_scan_add(const int* __restrict__ bsum, int n, int total,
                           int* rowptr, int* cursor){
    int i = blockIdx.x*blockDim.x + threadIdx.x;
    if (i < n){
        int v = rowptr[i] + bsum[i >> 9];
        rowptr[i] = v; cursor[i] = v;
    }
    if (i == 0) rowptr[n] = total;
}

// ---------------- fused weight prep ----------------
__global__ void k_prep_w_all(const float* __restrict__ W0, const float* __restrict__ W1,
                             const float* __restrict__ W2, const float* __restrict__ W3,
                             const float* __restrict__ W4, const float* __restrict__ W5,
                             const float* __restrict__ W6, const float* __restrict__ W7,
                             float* __restrict__ out){
    const float* warr[8] = {W0, W1, W2, W3, W4, W5, W6, W7};
    int slot = blockIdx.y;
    int b = slot >> 3, wsel = slot & 7;
    const float* W = warr[wsel] + (size_t)b*16384;
    int i = blockIdx.x*256 + threadIdx.x;
    int n = i >> 7, k = i & 127;
    out[(size_t)slot*16384 + i] = to_tf32(W[(size_t)k*DD + n]);
}

// ---------------- tf32 GEMM ----------------
#define GSM 101376
#define SB_OFF 33792

template<int KIND>
__global__ __launch_bounds__(256, 2) void k_gemm(
        const float* __restrict__ A, int rows,
        const float* __restrict__ B0, const float* __restrict__ B1, const float* __restrict__ B2,
        float* __restrict__ O0, float* __restrict__ O1, float* __restrict__ O2,
        __nv_bfloat16* __restrict__ O2b,
        const int* __restrict__ mid, const float* __restrict__ p2mn,
        float* __restrict__ copy_out){
    extern __shared__ char sp[];
    float* sA = (float*)sp;
    float* sB = (float*)(sp + SB_OFF);
    const uint32_t* sAu = (const uint32_t*)sA;
    const uint32_t* sBu = (const uint32_t*)sB;
    int tid = threadIdx.x, wid = tid >> 5, lane = tid & 31;
    int row0 = blockIdx.x*64;
    int g = lane >> 2, t = lane & 3;
    int m0 = (wid >> 2)*32, n0 = (wid & 3)*32;

    for (int i = tid; i < 2048; i += 256){
        int r = i >> 5, c4 = i & 31;
        float4 v = make_float4(0,0,0,0);
        if (row0 + r < rows) v = *(const float4*)(A + (size_t)(row0+r)*DD + c4*4);
        v.x = to_tf32(v.x); v.y = to_tf32(v.y); v.z = to_tf32(v.z); v.w = to_tf32(v.w);
        *(float4*)(sA + r*132 + c4*4) = v;
    }

    const float* Bp[3] = {B0, B1, B2};
    float* Op[3] = {O0, O1, O2};
    const int NWT = (KIND == 0) ? 3 : 1;

    #pragma unroll
    for (int iw = 0; iw < NWT; iw++){
        __syncthreads();
        const float* Bsrc = Bp[iw];
        for (int i = tid; i < 4096; i += 256){
            int n = i >> 5, c4 = i & 31;
            *(float4*)(sB + n*132 + c4*4) = ((const float4*)Bsrc)[i];
        }
        __syncthreads();

        float acc[2][4][4];
        #pragma unroll
        for (int mt = 0; mt < 2; mt++)
            #pragma unroll
            for (int nt = 0; nt < 4; nt++)
                #pragma unroll
                for (int j = 0; j < 4; j++) acc[mt][nt][j] = 0.0f;

        #pragma unroll
        for (int ks = 0; ks < 16; ks++){
            int k0 = ks*8;
            uint32_t a[2][4], b[4][2];
            #pragma unroll
            for (int mt = 0; mt < 2; mt++){
                int base = (m0 + mt*16 + g)*132 + k0 + t;
                a[mt][0] = sAu[base];
                a[mt][1] = sAu[base + 8*132];
                a[mt][2] = sAu[base + 4];
                a[mt][3] = sAu[base + 8*132 + 4];
            }
            #pragma unroll
            for (int nt = 0; nt < 4; nt++){
                int nb = (n0 + nt*8 + g)*132 + k0 + t;
                b[nt][0] = sBu[nb];
                b[nt][1] = sBu[nb + 4];
            }
            #pragma unroll
            for (int mt = 0; mt < 2; mt++)
                #pragma unroll
                for (int nt = 0; nt < 4; nt++)
                    mma_tf32(acc[mt][nt], a[mt], b[nt]);
        }

        float* O = Op[iw];
        bool isq = (KIND == 0) && (iw == 0);
        bool isvb = (KIND == 0) && (iw == 2) && (O2b != nullptr);
        #pragma unroll
        for (int mt = 0; mt < 2; mt++){
            #pragma unroll
            for (int half = 0; half < 2; half++){
                int gr = row0 + m0 + mt*16 + g + half*8;
                if (gr >= rows) continue;
                const float* pmrow = nullptr;
                if (isq && p2mn) pmrow = p2mn + (size_t)mid[gr]*DD;
                #pragma unroll
                for (int nt = 0; nt < 4; nt++){
                    int cc = n0 + nt*8 + t*2;
                    float v0 = acc[mt][nt][half*2 + 0];
                    float v1 = acc[mt][nt][half*2 + 1];
                    size_t gi = (size_t)gr*DD + cc;
                    if (KIND == 0){
                        if (isq){
                            float b0 = g_base.n2[cc], b1 = g_base.n2[cc+1];
                            if (pmrow){ b0 += pmrow[cc]; b1 += pmrow[cc+1]; }
                            v0 *= b0; v1 *= b1;
                        }
                        if (isvb){
                            __nv_bfloat162 hv = __floats2bfloat162_rn(v0, v1);
                            *(uint32_t*)((char*)O2b + gi*2) = *(uint32_t*)&hv;
                        } else {
                            *(float2*)(O + gi) = make_float2(v0, v1);
                        }
                    } else {
                        v0 = fmaxf(v0, 0.0f); v1 = fmaxf(v1, 0.0f);
                        if (copy_out) *(float2*)(copy_out + gi) = make_float2(v0, v1);
                        float2 f = *(float2*)(O + gi);
                        f.x += v0; f.y += v1;
                        *(float2*)(O + gi) = f;
                    }
                }
            }
        }
    }
}

// ---------------- meta learner ----------------
__device__ __forceinline__ void warp_ml_weights(float4 xv, int lane,
        const float* __restrict__ u, float* s){
    #pragma unroll
    for (int l2 = 0; l2 < LL; l2++){
        float4 uv = *(const float4*)(u + l2*DD + lane*4);
        float p = xv.x*uv.x + xv.y*uv.y + xv.z*uv.z + xv.w*uv.w;
        p += __shfl_xor_sync(0xffffffffu, p, 1);
        p += __shfl_xor_sync(0xffffffffu, p, 2);
        p += __shfl_xor_sync(0xffffffffu, p, 4);
        p += __shfl_xor_sync(0xffffffffu, p, 8);
        p += __shfl_xor_sync(0xffffffffu, p, 16);
        s[l2] = p * RSQD;
    }
    float mx = s[0];
    #pragma unroll
    for (int i = 1; i < LL; i++) mx = fmaxf(mx, s[i]);
    float zz = 0.0f;
    #pragma unroll
    for (int i = 0; i < LL; i++){ s[i] = __expf(s[i]-mx); zz += s[i]; }
    float inv = 1.0f / zz;
    #pragma unroll
    for (int i = 0; i < LL; i++) s[i] *= inv;
}

__device__ __forceinline__ void warp_meta_learner(float4 xv, int lane,
        const float* __restrict__ u, const float* __restrict__ W2, const float* __restrict__ W1,
        float* p2_out, float* p1_out){
    float s[LL];
    warp_ml_weights(xv, lane, u, s);
    if (p2_out){
        float4 acc = make_float4(0,0,0,0);
        #pragma unroll
        for (int l2 = 0; l2 < LL; l2++){
            float4 wv = *(const float4*)(W2 + l2*DD + lane*4);
            acc.x += s[l2]*wv.x; acc.y += s[l2]*wv.y; acc.z += s[l2]*wv.z; acc.w += s[l2]*wv.w;
        }
        *(float4*)(p2_out + lane*4) = acc;
    }
    if (p1_out && lane < HH){
        float a = 0.0f;
        #pragma unroll
        for (int l2 = 0; l2 < LL; l2++) a += s[l2]*W1[l2*HH + lane];
        p1_out[lane] = a;
    }
}

// fused: rows [0,MNN) node (fp32), rows [MNN,MNN+MEE) edge (bf16)
__global__ void k_meta_learner_all(const float* __restrict__ Xn, const float* __restrict__ Xe,
                                   const float* __restrict__ u, const float* __restrict__ W2,
                                   const float* __restrict__ W1,
                                   float* __restrict__ p2n, float* __restrict__ p1n,
                                   __nv_bfloat16* __restrict__ p2e, __nv_bfloat16* __restrict__ p1e){
    int w = (blockIdx.x*blockDim.x + threadIdx.x) >> 5;
    int lane = threadIdx.x & 31;
    if (w < MNN){
        float4 xv = *(const float4*)(Xn + (size_t)w*DD + lane*4);
        warp_meta_learner(xv, lane, u, W2, W1, p2n + (size_t)w*DD, p1n + (size_t)w*HH);
    } else if (w < MNN + MEE){
        int we = w - MNN;
        float4 xv = *(const float4*)(Xe + (size_t)we*DD + lane*4);
        float s[LL];
        warp_ml_weights(xv, lane, u, s);
        float4 acc = make_float4(0,0,0,0);
        #pragma unroll
        for (int l2 = 0; l2 < LL; l2++){
            float4 wv = *(const float4*)(W2 + l2*DD + lane*4);
            acc.x += s[l2]*wv.x; acc.y += s[l2]*wv.y; acc.z += s[l2]*wv.z; acc.w += s[l2]*wv.w;
        }
        __nv_bfloat162 h0 = __floats2bfloat162_rn(acc.x, acc.y);
        __nv_bfloat162 h1 = __floats2bfloat162_rn(acc.z, acc.w);
        uint2 pk; pk.x = *(uint32_t*)&h0; pk.y = *(uint32_t*)&h1;
        *(uint2*)(p2e + (size_t)we*DD + lane*4) = pk;
        if (lane < HH){
            float a = 0.0f;
            #pragma unroll
            for (int l2 = 0; l2 < LL; l2++) a += s[l2]*W1[l2*HH + lane];
            p1e[(size_t)we*HH + lane] = __float2bfloat16(a);
        }
    }
}

// static graph -> base params; 6 warps: warp0 aggregates, warps 0-4 then do params in parallel
__global__ void k_static(const float* __restrict__ emb, const int* __restrict__ svals,
                         const int* __restrict__ ssrc, const int* __restrict__ sdst,
                         const float* __restrict__ u, const float* __restrict__ W2,
                         const float* __restrict__ W1){
    __shared__ float sagg[VPP][DD];
    int tid = threadIdx.x, wid = tid >> 5, lane = tid & 31;
    for (int i = tid; i < VPP*DD; i += 192) ((float*)sagg)[i] = 0.0f;
    __syncthreads();
    if (wid == 0){
        for (int e = 0; e < SEE; e++){
            int rdst = sdst[e];
            const float* ev = emb + (size_t)svals[ssrc[e]]*DD;
            for (int c = lane; c < DD; c += 32) sagg[rdst][c] += ev[c];
        }
    }
    __syncthreads();
    if (wid < 5){
        const int rows[5] = {0, 3, 6, 9, 12};
        float4 x = *(float4*)&sagg[rows[wid]][lane*4];
        if (wid == 0)      warp_meta_learner(x, lane, u, W2, W1, nullptr,   g_base.tw);
        else if (wid == 1) warp_meta_learner(x, lane, u, W2, W1, nullptr,   g_base.n1);
        else if (wid == 2) warp_meta_learner(x, lane, u, W2, W1, g_base.n2, nullptr);
        else if (wid == 3) warp_meta_learner(x, lane, u, W2, W1, nullptr,   g_base.e1);
        else               warp_meta_learner(x, lane, u, W2, W1, g_base.e2, nullptr);
    }
}

// ---------------- edge conv: warp/dst-node, anchored-shift softmax, 2-way interleave ----------------
// Shift anchored at first edge's score (softmax is shift-invariant; in-node score spread << 80).
template<bool META>
__global__ void k_edge_conv(const int* __restrict__ rowptr,
                            const int* __restrict__ es, const int* __restrict__ em,
                            const int* __restrict__ mid_arr,
                            const float* __restrict__ q, const float* __restrict__ kf,
                            const float* __restrict__ vf, const __nv_bfloat16* __restrict__ vb,
                            const __nv_bfloat16* __restrict__ p2me,
                            const __nv_bfloat16* __restrict__ p1me,
                            const float* __restrict__ p1mn,
                            float* __restrict__ agg, float* __restrict__ keout, int n){
    int node = blockIdx.x*(blockDim.x >> 5) + (threadIdx.x >> 5);
    if (node >= n) return;
    int lane = threadIdx.x & 31, h = lane >> 2;
    int i0 = rowptr[node], i1 = rowptr[node+1];
    if (i0 == i1){
        *(float4*)(agg + (size_t)node*DD + lane*4) = make_float4(0,0,0,0);
        return;
    }
    float4 qv = *(const float4*)(q + (size_t)node*DD + lane*4);
    float p1n = g_base.n1[h];
    if (!META) p1n += p1mn[(size_t)mid_arr[node]*HH + h];
    float4 be2 = *(float4*)&g_base.e2[lane*4];
    float be1 = g_base.e1[h];

    // --- first edge: anchor shift m = its score; w = 1 ---
    float m;
    float zA, zB = 0.0f;
    float4 accA, accB = make_float4(0,0,0,0);
    {
        int s0 = es[i0], e0 = em[i0];
        float4 kv0 = *(const float4*)(kf + (size_t)s0*DD + lane*4);
        float4 vv0;
        if (META) vv0 = *(const float4*)(vf + (size_t)s0*DD + lane*4);
        else      vv0 = bf4_to_f4(*(const uint2*)(vb + (size_t)s0*DD + lane*4));
        float4 p20 = be2; float e10 = be1;
        if (!META){
            float4 a0 = bf4_to_f4(*(const uint2*)(p2me + (size_t)e0*DD + lane*4));
            p20.x += a0.x; p20.y += a0.y; p20.z += a0.z; p20.w += a0.w;
            e10 += __bfloat162float(p1me[(size_t)e0*HH + h]);
        }
        float4 ke0;
        ke0.x = kv0.x*p20.x; ke0.y = kv0.y*p20.y; ke0.z = kv0.z*p20.z; ke0.w = kv0.w*p20.w;
        if (META) *(float4*)(keout + (size_t)e0*DD + lane*4) = ke0;
        float d0 = qv.x*ke0.x + qv.y*ke0.y + qv.z*ke0.z + qv.w*ke0.w;
        d0 += __shfl_xor_sync(0xffffffffu, d0, 1);
        d0 += __shfl_xor_sync(0xffffffffu, d0, 2);
        m = d0*0.25f + e10 + p1n;
        zA = 1.0f;
        accA = vv0;
    }

    int i = i0 + 1;
    for (; i + 1 < i1; i += 2){
        int s0 = es[i],  s1 = es[i+1];
        int e0 = em[i],  e1v = em[i+1];
        float4 kv0 = *(const float4*)(kf + (size_t)s0*DD + lane*4);
        float4 kv1 = *(const float4*)(kf + (size_t)s1*DD + lane*4);
        float4 vv0, vv1;
        if (META){
            vv0 = *(const float4*)(vf + (size_t)s0*DD + lane*4);
            vv1 = *(const float4*)(vf + (size_t)s1*DD + lane*4);
        } else {
            vv0 = bf4_to_f4(*(const uint2*)(vb + (size_t)s0*DD + lane*4));
            vv1 = bf4_to_f4(*(const uint2*)(vb + (size_t)s1*DD + lane*4));
        }
        float4 p20 = be2, p21 = be2;
        float e10 = be1, e11 = be1;
        if (!META){
            float4 a0 = bf4_to_f4(*(const uint2*)(p2me + (size_t)e0*DD  + lane*4));
            float4 a1 = bf4_to_f4(*(const uint2*)(p2me + (size_t)e1v*DD + lane*4));
            p20.x += a0.x; p20.y += a0.y; p20.z += a0.z; p20.w += a0.w;
            p21.x += a1.x; p21.y += a1.y; p21.z += a1.z; p21.w += a1.w;
            e10 += __bfloat162float(p1me[(size_t)e0*HH + h]);
            e11 += __bfloat162float(p1me[(size_t)e1v*HH + h]);
        }
        float4 ke0, ke1;
        ke0.x = kv0.x*p20.x; ke0.y = kv0.y*p20.y; ke0.z = kv0.z*p20.z; ke0.w = kv0.w*p20.w;
        ke1.x = kv1.x*p21.x; ke1.y = kv1.y*p21.y; ke1.z = kv1.z*p21.z; ke1.w = kv1.w*p21.w;
        if (META){
            *(float4*)(keout + (size_t)e0*DD  + lane*4) = ke0;
            *(float4*)(keout + (size_t)e1v*DD + lane*4) = ke1;
        }
        float d0 = qv.x*ke0.x + qv.y*ke0.y + qv.z*ke0.z + qv.w*ke0.w;
        float d1 = qv.x*ke1.x + qv.y*ke1.y + qv.z*ke1.z + qv.w*ke1.w;
        d0 += __shfl_xor_sync(0xffffffffu, d0, 1);
        d1 += __shfl_xor_sync(0xffffffffu, d1, 1);
        d0 += __shfl_xor_sync(0xffffffffu, d0, 2);
        d1 += __shfl_xor_sync(0xffffffffu, d1, 2);
        float w0 = __expf(d0*0.25f + e10 + p1n - m);
        float w1 = __expf(d1*0.25f + e11 + p1n - m);
        accA.x += vv0.x*w0; accA.y += vv0.y*w0; accA.z += vv0.z*w0; accA.w += vv0.w*w0;
        accB.x += vv1.x*w1; accB.y += vv1.y*w1; accB.z += vv1.z*w1; accB.w += vv1.w*w1;
        zA += w0; zB += w1;
    }
    if (i < i1){
        int s0 = es[i], e0 = em[i];
        float4 kv0 = *(const float4*)(kf + (size_t)s0*DD + lane*4);
        float4 vv0;
        if (META) vv0 = *(const float4*)(vf + (size_t)s0*DD + lane*4);
        else      vv0 = bf4_to_f4(*(const uint2*)(vb + (size_t)s0*DD + lane*4));
        float4 p20 = be2; float e10 = be1;
        if (!META){
            float4 a0 = bf4_to_f4(*(const uint2*)(p2me + (size_t)e0*DD + lane*4));
            p20.x += a0.x; p20.y += a0.y; p20.z += a0.z; p20.w += a0.w;
            e10 += __bfloat162float(p1me[(size_t)e0*HH + h]);
        }
        float4 ke0;
        ke0.x = kv0.x*p20.x; ke0.y = kv0.y*p20.y; ke0.z = kv0.z*p20.z; ke0.w = kv0.w*p20.w;
        if (META) *(float4*)(keout + (size_t)e0*DD + lane*4) = ke0;
        float d0 = qv.x*ke0.x + qv.y*ke0.y + qv.z*ke0.z + qv.w*ke0.w;
        d0 += __shfl_xor_sync(0xffffffffu, d0, 1);
        d0 += __shfl_xor_sync(0xffffffffu, d0, 2);
        float w0 = __expf(d0*0.25f + e10 + p1n - m);
        accA.x += vv0.x*w0; accA.y += vv0.y*w0; accA.z += vv0.z*w0; accA.w += vv0.w*w0;
        zA += w0;
    }
    float z = zA + zB;
    float inv = 1.0f / (z + 1e-9f);
    float4 o;
    o.x = (accA.x + accB.x)*inv; o.y = (accA.y + accB.y)*inv;
    o.z = (accA.z + accB.z)*inv; o.w = (accA.w + accB.w)*inv;
    *(float4*)(agg + (size_t)node*DD + lane*4) = o;
}

__global__ void k_readout(const float* __restrict__ feat, const int* __restrict__ tix,
                          const int* __restrict__ mid_arr, const float* __restrict__ p1mn,
                          float* __restrict__ out, int first){
    int t = blockIdx.x*(blockDim.x >> 5) + (threadIdx.x >> 5);
    if (t >= BTT) return;
    int lane = threadIdx.x & 31, h = lane >> 2;
    int ti = tix[t];
    float4 f = *(const float4*)(feat + (size_t)ti*DD + lane*4);
    float s4 = f.x + f.y + f.z + f.w;
    float tw = g_base.tw[h] + p1mn[(size_t)mid_arr[ti]*HH + h];
    float p = tw * s4;
    p += __shfl_xor_sync(0xffffffffu, p, 1);
    p += __shfl_xor_sync(0xffffffffu, p, 2);
    p += __shfl_xor_sync(0xffffffffu, p, 4);
    p += __shfl_xor_sync(0xffffffffu, p, 8);
    p += __shfl_xor_sync(0xffffffffu, p, 16);
    if (lane == 0){
        if (first) out[t] = 0.5f * p;
        else       out[t] += 0.5f * p;
    }
}

// ---------------- host ----------------
extern "C" void kernel_launch(void* const* d_in, const int* in_sizes, int n_in,
                              void* d_out, int out_size){
    (void)in_sizes; (void)n_in; (void)out_size;
    const float* emb  = (const float*)d_in[0];
    const float* u    = (const float*)d_in[1];
    const float* W2l  = (const float*)d_in[2];
    const float* W1l  = (const float*)d_in[3];
    const float* Wq_m = (const float*)d_in[4];
    const float* Wk_m = (const float*)d_in[5];
    const float* Wv_m = (const float*)d_in[6];
    const float* Wo_m = (const float*)d_in[7];
    const float* Wq   = (const float*)d_in[8];
    const float* Wk   = (const float*)d_in[9];
    const float* Wv   = (const float*)d_in[10];
    const float* Wo   = (const float*)d_in[11];
    const int* node_vals      = (const int*)d_in[12];
    const int* meta_node_vals = (const int*)d_in[13];
    const int* srcv = (const int*)d_in[14];
    const int* dstv = (const int*)d_in[15];
    const int* msrc = (const int*)d_in[16];
    const int* mdst = (const int*)d_in[17];
    const int* mnid = (const int*)d_in[18];
    const int* meid = (const int*)d_in[19];
    const int* tix  = (const int*)d_in[20];
    const int* svals= (const int*)d_in[21];
    const int* ssrc = (const int*)d_in[22];
    const int* sdst = (const int*)d_in[23];
    float* out = (float*)d_out;

    void* vp;
    cudaGetSymbolAddress(&vp, g_feat);   float* p_feat  = (float*)vp;
    cudaGetSymbolAddress(&vp, g_q);      float* p_q     = (float*)vp;
    cudaGetSymbolAddress(&vp, g_k);      float* p_k     = (float*)vp;
    cudaGetSymbolAddress(&vp, g_vb);     __nv_bfloat16* p_vb = (__nv_bfloat16*)vp;
    cudaGetSymbolAddress(&vp, g_agg);    float* p_agg   = (float*)vp;
    cudaGetSymbolAddress(&vp, g_mfeat);  float* p_mfeat = (float*)vp;
    cudaGetSymbolAddress(&vp, g_mq);     float* p_mq    = (float*)vp;
    cudaGetSymbolAddress(&vp, g_mk);     float* p_mk    = (float*)vp;
    cudaGetSymbolAddress(&vp, g_mv);     float* p_mv    = (float*)vp;
    cudaGetSymbolAddress(&vp, g_magg);   float* p_magg  = (float*)vp;
    cudaGetSymbolAddress(&vp, g_mout);   float* p_mout  = (float*)vp;
    cudaGetSymbolAddress(&vp, g_mef);    float* p_mef   = (float*)vp;
    cudaGetSymbolAddress(&vp, g_p2mn);   float* p_p2mn  = (float*)vp;
    cudaGetSymbolAddress(&vp, g_p1mn);   float* p_p1mn  = (float*)vp;
    cudaGetSymbolAddress(&vp, g_p2meb);  __nv_bfloat16* p_p2meb = (__nv_bfloat16*)vp;
    cudaGetSymbolAddress(&vp, g_p1meb);  __nv_bfloat16* p_p1meb = (__nv_bfloat16*)vp;
    cudaGetSymbolAddress(&vp, g_deg);     int* p_deg    = (int*)vp;
    cudaGetSymbolAddress(&vp, g_rowptr);  int* p_rowptr = (int*)vp;
    cudaGetSymbolAddress(&vp, g_cursor);  int* p_cursor = (int*)vp;
    cudaGetSymbolAddress(&vp, g_esrc);    int* p_esrc   = (int*)vp;
    cudaGetSymbolAddress(&vp, g_emid);    int* p_emid   = (int*)vp;
    cudaGetSymbolAddress(&vp, g_mdeg);    int* p_mdeg   = (int*)vp;
    cudaGetSymbolAddress(&vp, g_mrowptr); int* p_mrowptr= (int*)vp;
    cudaGetSymbolAddress(&vp, g_mcursor); int* p_mcursor= (int*)vp;
    cudaGetSymbolAddress(&vp, g_mesrc);   int* p_mesrc  = (int*)vp;
    cudaGetSymbolAddress(&vp, g_meid);    int* p_meid   = (int*)vp;
    cudaGetSymbolAddress(&vp, g_bsum);    int* p_bsum   = (int*)vp;
    cudaGetSymbolAddress(&vp, g_mbsum);   int* p_mbsum  = (int*)vp;
    cudaGetSymbolAddress(&vp, g_bwf);     float* p_bwf  = (float*)vp;

    cudaFuncSetAttribute(k_gemm<0>, cudaFuncAttributeMaxDynamicSharedMemorySize, GSM);
    cudaFuncSetAttribute(k_gemm<1>, cudaFuncAttributeMaxDynamicSharedMemorySize, GSM);

    // CSR (both graphs, fused)
    k_zero2<<<(NN+MNN+255)/256, 256>>>(p_deg, NN, p_mdeg, MNN);
    k_hist2<<<(EE+MEE+255)/256, 256>>>(dstv, mdst, p_deg, p_mdeg);
    {
        int nb = (NN + 511)/512;
        k_scan_local<<<nb, 512>>>(p_deg, NN, p_rowptr, p_bsum);
        k_scan_bsum<<<1, 256>>>(p_bsum, nb);
        k_scan_add<<<(NN+255)/256, 256>>>(p_bsum, NN, EE, p_rowptr, p_cursor);
        int mb = (MNN + 511)/512;
        k_scan_local<<<mb, 512>>>(p_mdeg, MNN, p_mrowptr, p_mbsum);
        k_scan_bsum<<<1, 256>>>(p_mbsum, mb);
        k_scan_add<<<(MNN+255)/256, 256>>>(p_mbsum, MNN, MEE, p_mrowptr, p_mcursor);
    }
    k_scatter_all<<<(EE+MEE+255)/256, 256>>>(dstv, srcv, meid, mdst, msrc,
                                             p_cursor, p_esrc, p_emid,
                                             p_mcursor, p_mesrc, p_meid);

    // gather embeddings (fused)
    k_gather2<<<((NN+MNN)*32+255)/256, 256>>>(emb, node_vals, meta_node_vals, p_feat, p_mfeat);

    // base params (5 warps in parallel)
    k_static<<<1, 192>>>(emb, svals, ssrc, sdst, u, W2l, W1l);

    // weight prep (one launch)
    {
        dim3 gp(64, 16);
        k_prep_w_all<<<gp, 256>>>(Wq_m, Wk_m, Wv_m, Wo_m, Wq, Wk, Wv, Wo, p_bwf);
    }

    #define BW(b, wsel) (p_bwf + (size_t)((b)*8+(wsel))*16384)

    int tmain = (NN + 63)/64;
    int tmeta = (MNN + 63)/64;
    for (int b = 0; b < 2; b++){
        // meta conv (all fp32)
        k_gemm<0><<<tmeta, 256, GSM>>>(p_mfeat, MNN, BW(b,0), BW(b,1), BW(b,2),
                                       p_mq, p_mk, p_mv, nullptr, nullptr, nullptr, nullptr);
        k_edge_conv<true><<<(MNN+7)/8, 256>>>(p_mrowptr, p_mesrc, p_meid, nullptr,
                                              p_mq, p_mk, p_mv, nullptr, nullptr, nullptr,
                                              nullptr, p_magg, p_mef, MNN);
        k_gemm<1><<<tmeta, 256, GSM>>>(p_magg, MNN, BW(b,3), nullptr, nullptr,
                                       p_mfeat, nullptr, nullptr, nullptr,
                                       nullptr, nullptr, p_mout);

        // meta learners (fused node fp32 + edge bf16)
        k_meta_learner_all<<<((MNN+MEE)*32+255)/256, 256>>>(p_mout, p_mef, u, W2l, W1l,
                                                            p_p2mn, p_p1mn, p_p2meb, p_p1meb);

        // main conv (v in bf16)
        k_gemm<0><<<tmain, 256, GSM>>>(p_feat, NN, BW(b,4), BW(b,5), BW(b,6),
                                       p_q, p_k, nullptr, p_vb, mnid, p_p2mn, nullptr);
        k_edge_conv<false><<<(NN+7)/8, 256>>>(p_rowptr, p_esrc, p_emid, mnid,
                                              p_q, p_k, nullptr, p_vb, p_p2meb, p_p1meb,
                                              p_p1mn, p_agg, nullptr, NN);
        k_gemm<1><<<tmain, 256, GSM>>>(p_agg, NN, BW(b,7), nullptr, nullptr,
                                       p_feat, nullptr, nullptr, nullptr,
                                       nullptr, nullptr, nullptr);

        // readout
        k_readout<<<(BTT+7)/8, 256>>>(p_feat, tix, mnid, p_p1mn, out, b == 0 ? 1 : 0);
    }
    #undef BW
}